// round 9
// baseline (speedup 1.0000x reference)
#include <cuda_runtime.h>
#include <math.h>

#define B_   4
#define N_   4096
#define H_   12
#define DH_  64
#define NB_  266
#define BH_  (B_*H_)           // 48
#define R_   (B_*H_*N_)        // 196608
#define EPS_ 1e-4f

// ---------------- scratch (static device memory; no allocation) ----------------
__device__ float g_q[R_ * DH_];            // 12.58M
__device__ float g_k[R_ * DH_];
__device__ float g_v[R_ * DH_];
__device__ float g_qp[R_ * NB_];           // 52.3M
__device__ float g_kp[R_ * NB_];           // 52.3M (raw dash, then exp in place)
__device__ float g_kdiag[R_];
__device__ float g_kmax[BH_];
__device__ float g_ksum_part[BH_ * 32 * NB_];
__device__ float g_ksum[BH_ * NB_];
__device__ float g_ctx_part[4 * BH_ * NB_ * DH_];
__device__ float g_ctx[BH_ * NB_ * DH_];

// ---------------- helpers ----------------
static __device__ __forceinline__ unsigned long long pk2(float lo, float hi) {
    unsigned long long r;
    asm("mov.b64 %0, {%1, %2};" : "=l"(r) : "f"(lo), "f"(hi));
    return r;
}
static __device__ __forceinline__ float2 upk2(unsigned long long v) {
    float2 r;
    asm("mov.b64 {%0, %1}, %2;" : "=f"(r.x), "=f"(r.y) : "l"(v));
    return r;
}
static __device__ __forceinline__ void ffma2(unsigned long long& d,
                                             unsigned long long a,
                                             unsigned long long b) {
    asm("fma.rn.f32x2 %0, %1, %2, %0;" : "+l"(d) : "l"(a), "l"(b));
}
static __device__ __forceinline__ void atomicMaxF(float* addr, float v) {
    if (v >= 0.f) atomicMax((int*)addr, __float_as_int(v));
    else          atomicMin((unsigned int*)addr, __float_as_uint(v));
}

__global__ void perf_init_kernel() {
    if (threadIdx.x < BH_) g_kmax[threadIdx.x] = -INFINITY;
}

// ---------------- fused QKV projection GEMM (f32x2 packed FMA) ----------------
// C[i,o] = sum_k hs[i,k] * W[o,k] + b[o]; store to [b,h,n,d] layout.
#define QBM 128
#define QBN 128
#define QBK 16

__global__ __launch_bounds__(256)
void perf_qkv_gemm(const float* __restrict__ A,
                   const float* __restrict__ Wq, const float* __restrict__ bq,
                   const float* __restrict__ Wk, const float* __restrict__ bk,
                   const float* __restrict__ Wv, const float* __restrict__ bv) {
    __shared__ float As[QBK][QBM + 4];
    __shared__ float Bs[QBK][QBN + 4];
    __shared__ float bias_s[QBN];

    int z = blockIdx.z;
    const float* W    = (z == 0) ? Wq : (z == 1) ? Wk : Wv;
    const float* bias = (z == 0) ? bq : (z == 1) ? bk : bv;
    float* dst        = (z == 0) ? g_q : (z == 1) ? g_k : g_v;

    int m0 = blockIdx.x * QBM;
    int o0 = blockIdx.y * QBN;
    int tid = threadIdx.x;
    if (tid < QBN) bias_s[tid] = bias[o0 + tid];
    int tx = tid & 15, ty = tid >> 4;

    unsigned long long acc2[8][4];
#pragma unroll
    for (int i = 0; i < 8; i++)
#pragma unroll
        for (int j = 0; j < 4; j++) acc2[i][j] = 0ull;

    for (int k0 = 0; k0 < 768; k0 += QBK) {
#pragma unroll
        for (int i = 0; i < 2; i++) {
            int id = i * 256 + tid;
            int r = id >> 2, c4 = (id & 3) * 4;
            float4 va = *(const float4*)(A + (size_t)(m0 + r) * 768 + k0 + c4);
            As[c4 + 0][r] = va.x; As[c4 + 1][r] = va.y;
            As[c4 + 2][r] = va.z; As[c4 + 3][r] = va.w;
            float4 vb = *(const float4*)(W + (size_t)(o0 + r) * 768 + k0 + c4);
            Bs[c4 + 0][r] = vb.x; Bs[c4 + 1][r] = vb.y;
            Bs[c4 + 2][r] = vb.z; Bs[c4 + 3][r] = vb.w;
        }
        __syncthreads();
#pragma unroll
        for (int k = 0; k < QBK; k++) {
            float4 a0 = *(float4*)(&As[k][ty * 4]);
            float4 a1 = *(float4*)(&As[k][64 + ty * 4]);
            float4 b0 = *(float4*)(&Bs[k][tx * 4]);
            float4 b1 = *(float4*)(&Bs[k][64 + tx * 4]);
            unsigned long long bp0 = pk2(b0.x, b0.y);
            unsigned long long bp1 = pk2(b0.z, b0.w);
            unsigned long long bp2 = pk2(b1.x, b1.y);
            unsigned long long bp3 = pk2(b1.z, b1.w);
            float av[8] = {a0.x, a0.y, a0.z, a0.w, a1.x, a1.y, a1.z, a1.w};
#pragma unroll
            for (int i = 0; i < 8; i++) {
                unsigned long long ad = pk2(av[i], av[i]);
                ffma2(acc2[i][0], ad, bp0);
                ffma2(acc2[i][1], ad, bp1);
                ffma2(acc2[i][2], ad, bp2);
                ffma2(acc2[i][3], ad, bp3);
            }
        }
        __syncthreads();
    }

#pragma unroll
    for (int i = 0; i < 8; i++) {
        int ml = (i < 4) ? (ty * 4 + i) : (64 + ty * 4 + i - 4);
        int gi = m0 + ml;
        int bb = gi >> 12, nn = gi & (N_ - 1);
#pragma unroll
        for (int g = 0; g < 2; g++) {
            int oc = g * 64 + tx * 4;    // column within [0,128)
            int o = o0 + oc;
            float2 p0 = upk2(acc2[i][g * 2 + 0]);
            float2 p1 = upk2(acc2[i][g * 2 + 1]);
            float4 v = make_float4(p0.x + bias_s[oc + 0], p0.y + bias_s[oc + 1],
                                   p1.x + bias_s[oc + 2], p1.y + bias_s[oc + 3]);
            int h = o >> 6, d = o & 63;
            *(float4*)(dst + ((size_t)(bb * H_ + h) * N_ + nn) * DH_ + d) = v;
        }
    }
}

// ---------------- FAVOR+ feature map: dash = (x*dn)·proj^T ----------------
// which==0: query path -> row-max, exp, write qp.
// which==1: key path   -> write raw dash to kp, save diag, atomicMax row-max into g_kmax[bh].
#define FEAT_SMEM ((288 * 68 + 8 * 64) * 4)

__global__ __launch_bounds__(256)
void perf_feat_kernel(const float* __restrict__ proj, int which) {
    extern __shared__ float sm[];
    float* ps = sm;               // proj, padded to 288 rows x stride 68
    float* qs = sm + 288 * 68;    // 8 rows x 64
    int tid = threadIdx.x;

    for (int i = tid; i < 288 * 17; i += 256) {
        int row = i / 17, c4 = i - row * 17;
        float4 v = make_float4(0.f, 0.f, 0.f, 0.f);
        if (row < NB_ && c4 < 16) v = *(const float4*)(proj + row * 64 + c4 * 4);
        *(float4*)(&ps[row * 68 + c4 * 4]) = v;
    }

    int w = tid >> 5, lane = tid & 31;
    int row = blockIdx.x * 8 + w;
    const float* src = which ? g_k : g_q;
    float* dstp      = which ? g_kp : g_qp;
    const float* qr = src + (size_t)row * DH_;
    float qa = qr[lane], qb = qr[32 + lane];
    qs[w * 64 + lane] = qa;
    qs[w * 64 + 32 + lane] = qb;
    __syncthreads();

    // diag = 0.5 * dn^2 * sum(x^2), dn^2 = 1/8 exactly
    float ss = qa * qa + qb * qb;
#pragma unroll
    for (int o = 16; o; o >>= 1) ss += __shfl_xor_sync(0xffffffffu, ss, o);
    float diag = 0.0625f * ss;

    float acc[9];
#pragma unroll
    for (int t = 0; t < 9; t++) acc[t] = 0.f;
#pragma unroll
    for (int d4 = 0; d4 < 16; d4++) {
        float4 q4 = *(float4*)(&qs[w * 64 + d4 * 4]);
#pragma unroll
        for (int t = 0; t < 9; t++) {
            float4 p = *(const float4*)(&ps[(lane + t * 32) * 68 + d4 * 4]);
            acc[t] += q4.x * p.x + q4.y * p.y + q4.z * p.z + q4.w * p.w;
        }
    }

    const float DN = 0.3535533905932738f;      // 64^-0.25
    const float RATIO = 0.06131393394849658f;  // 266^-0.5

    // row max of dash (= DN * max(acc), DN > 0); j >= 266 excluded
    float m = acc[0];
#pragma unroll
    for (int t = 1; t < 8; t++) m = fmaxf(m, acc[t]);
    if (lane < (NB_ - 256)) m = fmaxf(m, acc[8]);
#pragma unroll
    for (int o = 16; o; o >>= 1) m = fmaxf(m, __shfl_xor_sync(0xffffffffu, m, o));
    m *= DN;

    float* dr = dstp + (size_t)row * NB_;
    if (which == 0) {
#pragma unroll
        for (int t = 0; t < 9; t++) {
            int j = lane + t * 32;
            if (j < NB_) dr[j] = RATIO * (expf(acc[t] * DN - diag - m) + EPS_);
        }
    } else {
#pragma unroll
        for (int t = 0; t < 9; t++) {
            int j = lane + t * 32;
            if (j < NB_) dr[j] = acc[t] * DN;
        }
        if (lane == 0) {
            g_kdiag[row] = diag;
            atomicMaxF(&g_kmax[row >> 12], m);
        }
    }
}

// ---------------- K transform: kp = ratio*(exp(dash - diag - m_bh) + eps) in place ----
__global__ void perf_ktrans_kernel() {
    const float RATIO = 0.06131393394849658f;
    int idx = blockIdx.x * blockDim.x + threadIdx.x;
    const int total2 = R_ * NB_ / 2;
    if (idx >= total2) return;
    float2* p = ((float2*)g_kp) + idx;
    float2 v = *p;
    int e = idx * 2;
    int row = e / NB_;           // both elements of the float2 are in the same row
    float c = g_kdiag[row] + g_kmax[row >> 12];
    v.x = RATIO * (expf(v.x - c) + EPS_);
    v.y = RATIO * (expf(v.y - c) + EPS_);
    *p = v;
}

// ---------------- k_sum (deterministic two-stage) ----------------
__global__ void perf_ksumA_kernel() {
    int bh = blockIdx.y, ch = blockIdx.x, j = threadIdx.x;
    if (j >= NB_) return;
    const float* base = g_kp + ((size_t)(bh * N_ + ch * 128)) * NB_ + j;
    float s = 0.f;
#pragma unroll 4
    for (int r = 0; r < 128; r++) s += base[(size_t)r * NB_];
    g_ksum_part[(bh * 32 + ch) * NB_ + j] = s;
}

__global__ void perf_ksumB_kernel() {
    int bh = blockIdx.x, j = threadIdx.x;
    if (j >= NB_) return;
    float s = 0.f;
#pragma unroll
    for (int c = 0; c < 32; c++) s += g_ksum_part[(bh * 32 + c) * NB_ + j];
    g_ksum[bh * NB_ + j] = s;
}

// ---------------- ctx = kp^T v  (k-split tiled GEMM, partials) ----------------
__global__ __launch_bounds__(256)
void perf_ctx_kernel() {
    __shared__ float kt[16][68];
    __shared__ float vt[16][68];
    int jt = blockIdx.x, ks = blockIdx.y, bh = blockIdx.z;
    int j0 = jt * 64, n0 = ks * 1024;
    int tid = threadIdx.x, tx = tid & 15, ty = tid >> 4;
    const float* kbase = g_kp + (size_t)bh * N_ * NB_;
    const float* vbase = g_v + (size_t)bh * N_ * DH_;

    float acc[4][4];
#pragma unroll
    for (int a = 0; a < 4; a++)
#pragma unroll
        for (int b = 0; b < 4; b++) acc[a][b] = 0.f;

    for (int nn = 0; nn < 1024; nn += 16) {
#pragma unroll
        for (int i = 0; i < 2; i++) {
            int id = i * 256 + tid;
            int r = id >> 5, c2 = id & 31;
            int j = j0 + c2 * 2;
            float2 v = make_float2(0.f, 0.f);
            if (j + 1 < NB_)
                v = *(const float2*)(kbase + (size_t)(n0 + nn + r) * NB_ + j);
            kt[r][c2 * 2] = v.x;
            kt[r][c2 * 2 + 1] = v.y;
        }
        {
            int r = tid >> 4, c4 = tid & 15;
            float4 v = *(const float4*)(vbase + (size_t)(n0 + nn + r) * DH_ + c4 * 4);
            *(float4*)(&vt[r][c4 * 4]) = v;
        }
        __syncthreads();
#pragma unroll
        for (int k = 0; k < 16; k++) {
            float4 a = *(float4*)(&kt[k][ty * 4]);
            float4 b = *(float4*)(&vt[k][tx * 4]);
            acc[0][0] += a.x * b.x; acc[0][1] += a.x * b.y; acc[0][2] += a.x * b.z; acc[0][3] += a.x * b.w;
            acc[1][0] += a.y * b.x; acc[1][1] += a.y * b.y; acc[1][2] += a.y * b.z; acc[1][3] += a.y * b.w;
            acc[2][0] += a.z * b.x; acc[2][1] += a.z * b.y; acc[2][2] += a.z * b.z; acc[2][3] += a.z * b.w;
            acc[3][0] += a.w * b.x; acc[3][1] += a.w * b.y; acc[3][2] += a.w * b.z; acc[3][3] += a.w * b.w;
        }
        __syncthreads();
    }

    float* obase = g_ctx_part + (size_t)(ks * BH_ + bh) * NB_ * DH_;
#pragma unroll
    for (int jj = 0; jj < 4; jj++) {
        int j = j0 + ty * 4 + jj;
        if (j < NB_)
            *(float4*)(&obase[(size_t)j * DH_ + tx * 4]) =
                make_float4(acc[jj][0], acc[jj][1], acc[jj][2], acc[jj][3]);
    }
}

__global__ void perf_ctxred_kernel() {
    const int T = BH_ * NB_ * DH_;  // 817152
    int i = blockIdx.x * blockDim.x + threadIdx.x;
    if (i >= T) return;
    g_ctx[i] = g_ctx_part[i] + g_ctx_part[i + T] + g_ctx_part[i + 2 * T] + g_ctx_part[i + 3 * T];
}

// ---------------- out = (qp @ ctx) / (qp @ ksum), transpose back ----------------
#define OUT_SMEM ((NB_ * DH_ + 272 + 8 * 268) * 4)

__global__ __launch_bounds__(256)
void perf_out_kernel(float* __restrict__ out) {
    extern __shared__ float sm[];
    float* ctx_s = sm;                       // 266*64
    float* ksum_s = sm + NB_ * DH_;          // 272 (padded)
    float* qs = sm + NB_ * DH_ + 272;        // 8 x 268
    int tid = threadIdx.x, w = tid >> 5, lane = tid & 31;
    int row0 = blockIdx.x * 128;
    int bh = row0 >> 12;

    const float* cb = g_ctx + (size_t)bh * NB_ * DH_;
    for (int i = tid; i < NB_ * DH_ / 4; i += 256)
        *(float4*)(&ctx_s[i * 4]) = *(const float4*)(cb + i * 4);
    for (int i = tid; i < NB_; i += 256) ksum_s[i] = g_ksum[bh * NB_ + i];
    __syncthreads();

    int bb = bh / H_, h = bh - bb * H_;

    for (int it = 0; it < 16; it++) {
        int row = row0 + w * 16 + it;
        const float2* qr = (const float2*)(g_qp + (size_t)row * NB_);
        __syncwarp();
#pragma unroll
        for (int k = 0; k < 5; k++) {
            int t2 = lane + k * 32;
            if (t2 < NB_ / 2) {
                float2 v = qr[t2];
                qs[w * 268 + t2 * 2] = v.x;
                qs[w * 268 + t2 * 2 + 1] = v.y;
            }
        }
        __syncwarp();

        float ds = 0.f;
#pragma unroll
        for (int t = 0; t < 9; t++) {
            int j = lane + t * 32;
            if (j < NB_) ds += qs[w * 268 + j] * ksum_s[j];
        }
#pragma unroll
        for (int o = 16; o; o >>= 1) ds += __shfl_xor_sync(0xffffffffu, ds, o);
        float dinv = 1.0f / ds;

        float ax = 0.f, ay = 0.f;
#pragma unroll 2
        for (int j = 0; j < NB_; j++) {
            float qv = qs[w * 268 + j];
            float2 c = *(const float2*)(&ctx_s[j * 64 + 2 * lane]);
            ax += qv * c.x;
            ay += qv * c.y;
        }

        int n = row & (N_ - 1);
        float2 o2 = make_float2(ax * dinv, ay * dinv);
        *(float2*)(out + ((size_t)(bb * N_ + n)) * 768 + h * 64 + 2 * lane) = o2;
    }
}

// ---------------- launch ----------------
extern "C" void kernel_launch(void* const* d_in, const int* in_sizes, int n_in,
                              void* d_out, int out_size) {
    (void)in_sizes; (void)n_in; (void)out_size;
    const float* hs   = (const float*)d_in[0];
    const float* Wq   = (const float*)d_in[1];
    const float* bq   = (const float*)d_in[2];
    const float* Wk   = (const float*)d_in[3];
    const float* bk   = (const float*)d_in[4];
    const float* Wv   = (const float*)d_in[5];
    const float* bv   = (const float*)d_in[6];
    const float* proj = (const float*)d_in[7];
    float* out = (float*)d_out;

    cudaFuncSetAttribute(perf_feat_kernel, cudaFuncAttributeMaxDynamicSharedMemorySize, FEAT_SMEM);
    cudaFuncSetAttribute(perf_out_kernel,  cudaFuncAttributeMaxDynamicSharedMemorySize, OUT_SMEM);

    perf_init_kernel<<<1, 64>>>();
    perf_qkv_gemm<<<dim3(128, 6, 3), 256>>>(hs, Wq, bq, Wk, bk, Wv, bv);
    perf_feat_kernel<<<R_ / 8, 256, FEAT_SMEM>>>(proj, 0);   // qp
    perf_feat_kernel<<<R_ / 8, 256, FEAT_SMEM>>>(proj, 1);   // k dash (raw) + max
    perf_ktrans_kernel<<<(R_ * NB_ / 2) / 256, 256>>>();
    perf_ksumA_kernel<<<dim3(32, BH_), 288>>>();
    perf_ksumB_kernel<<<BH_, 288>>>();
    perf_ctx_kernel<<<dim3(5, 4, BH_), 256>>>();
    perf_ctxred_kernel<<<(BH_ * NB_ * DH_ + 255) / 256, 256>>>();
    perf_out_kernel<<<R_ / 128, 256, OUT_SMEM>>>(out);
}

// round 10
// speedup vs baseline: 1.4445x; 1.4445x over previous
#include <cuda_runtime.h>
#include <math.h>

#define B_   4
#define N_   4096
#define H_   12
#define DH_  64
#define NB_  266
#define BH_  (B_*H_)           // 48
#define R_   (B_*H_*N_)        // 196608
#define EPS_ 1e-4f

// ---------------- scratch (static device memory; no allocation) ----------------
__device__ float g_q[R_ * DH_];
__device__ float g_k[R_ * DH_];
__device__ float g_v[R_ * DH_];
__device__ float g_qp[R_ * NB_];
__device__ float g_kp[R_ * NB_];           // raw dash, then exp in place
__device__ float g_kdiag[R_];
__device__ float g_kmax[BH_];
__device__ float g_ksum_part[BH_ * 32 * NB_];
__device__ float g_ksum[BH_ * NB_];
__device__ float g_ctx_part[4 * BH_ * NB_ * DH_];
__device__ float g_ctx[BH_ * NB_ * DH_];

// ---------------- helpers ----------------
static __device__ __forceinline__ unsigned long long pk2(float lo, float hi) {
    unsigned long long r;
    asm("mov.b64 %0, {%1, %2};" : "=l"(r) : "f"(lo), "f"(hi));
    return r;
}
static __device__ __forceinline__ float2 upk2(unsigned long long v) {
    float2 r;
    asm("mov.b64 {%0, %1}, %2;" : "=f"(r.x), "=f"(r.y) : "l"(v));
    return r;
}
static __device__ __forceinline__ void ffma2(unsigned long long& d,
                                             unsigned long long a,
                                             unsigned long long b) {
    asm("fma.rn.f32x2 %0, %1, %2, %0;" : "+l"(d) : "l"(a), "l"(b));
}
static __device__ __forceinline__ void atomicMaxF(float* addr, float v) {
    if (v >= 0.f) atomicMax((int*)addr, __float_as_int(v));
    else          atomicMin((unsigned int*)addr, __float_as_uint(v));
}

__global__ void perf_init_kernel() {
    if (threadIdx.x < BH_) g_kmax[threadIdx.x] = -INFINITY;
}

// ---------------- fused QKV projection GEMM (f32x2 packed FMA) ----------------
#define QBM 128
#define QBN 128
#define QBK 16

__global__ __launch_bounds__(256)
void perf_qkv_gemm(const float* __restrict__ A,
                   const float* __restrict__ Wq, const float* __restrict__ bq,
                   const float* __restrict__ Wk, const float* __restrict__ bk,
                   const float* __restrict__ Wv, const float* __restrict__ bv) {
    __shared__ float As[QBK][QBM + 4];
    __shared__ float Bs[QBK][QBN + 4];
    __shared__ float bias_s[QBN];

    int z = blockIdx.z;
    const float* W    = (z == 0) ? Wq : (z == 1) ? Wk : Wv;
    const float* bias = (z == 0) ? bq : (z == 1) ? bk : bv;
    float* dst        = (z == 0) ? g_q : (z == 1) ? g_k : g_v;

    int m0 = blockIdx.x * QBM;
    int o0 = blockIdx.y * QBN;
    int tid = threadIdx.x;
    if (tid < QBN) bias_s[tid] = bias[o0 + tid];
    int tx = tid & 15, ty = tid >> 4;

    unsigned long long acc2[8][4];
#pragma unroll
    for (int i = 0; i < 8; i++)
#pragma unroll
        for (int j = 0; j < 4; j++) acc2[i][j] = 0ull;

    for (int k0 = 0; k0 < 768; k0 += QBK) {
#pragma unroll
        for (int i = 0; i < 2; i++) {
            int id = i * 256 + tid;
            int r = id >> 2, c4 = (id & 3) * 4;
            float4 va = *(const float4*)(A + (size_t)(m0 + r) * 768 + k0 + c4);
            As[c4 + 0][r] = va.x; As[c4 + 1][r] = va.y;
            As[c4 + 2][r] = va.z; As[c4 + 3][r] = va.w;
            float4 vb = *(const float4*)(W + (size_t)(o0 + r) * 768 + k0 + c4);
            Bs[c4 + 0][r] = vb.x; Bs[c4 + 1][r] = vb.y;
            Bs[c4 + 2][r] = vb.z; Bs[c4 + 3][r] = vb.w;
        }
        __syncthreads();
#pragma unroll
        for (int k = 0; k < QBK; k++) {
            float4 a0 = *(float4*)(&As[k][ty * 4]);
            float4 a1 = *(float4*)(&As[k][64 + ty * 4]);
            float4 b0 = *(float4*)(&Bs[k][tx * 4]);
            float4 b1 = *(float4*)(&Bs[k][64 + tx * 4]);
            unsigned long long bp0 = pk2(b0.x, b0.y);
            unsigned long long bp1 = pk2(b0.z, b0.w);
            unsigned long long bp2 = pk2(b1.x, b1.y);
            unsigned long long bp3 = pk2(b1.z, b1.w);
            float av[8] = {a0.x, a0.y, a0.z, a0.w, a1.x, a1.y, a1.z, a1.w};
#pragma unroll
            for (int i = 0; i < 8; i++) {
                unsigned long long ad = pk2(av[i], av[i]);
                ffma2(acc2[i][0], ad, bp0);
                ffma2(acc2[i][1], ad, bp1);
                ffma2(acc2[i][2], ad, bp2);
                ffma2(acc2[i][3], ad, bp3);
            }
        }
        __syncthreads();
    }

#pragma unroll
    for (int i = 0; i < 8; i++) {
        int ml = (i < 4) ? (ty * 4 + i) : (64 + ty * 4 + i - 4);
        int gi = m0 + ml;
        int bb = gi >> 12, nn = gi & (N_ - 1);
#pragma unroll
        for (int g = 0; g < 2; g++) {
            int oc = g * 64 + tx * 4;
            int o = o0 + oc;
            float2 p0 = upk2(acc2[i][g * 2 + 0]);
            float2 p1 = upk2(acc2[i][g * 2 + 1]);
            float4 v = make_float4(p0.x + bias_s[oc + 0], p0.y + bias_s[oc + 1],
                                   p1.x + bias_s[oc + 2], p1.y + bias_s[oc + 3]);
            int h = o >> 6, d = o & 63;
            *(float4*)(dst + ((size_t)(bb * H_ + h) * N_ + nn) * DH_ + d) = v;
        }
    }
}

// ---------------- FAVOR+ feature map (12-row x 3-tgroup blocked, f32x2) --------
// Block: 192 threads = 6 warps = 2 row-groups x 3 t-groups. Block covers 24 rows.
// blockIdx.y: 0 = query path, 1 = key path.
// smem floats: ps 288*68 | qs 24*64 | diag 24 | rowmax 24
#define FEAT_PS   (288 * 68)
#define FEAT_QS   (24 * 64)
#define FEAT_SMEM ((FEAT_PS + FEAT_QS + 24 + 24) * 4)

__global__ __launch_bounds__(192)
void perf_feat_kernel(const float* __restrict__ proj) {
    extern __shared__ float sm[];
    float* ps = sm;
    float* qs = sm + FEAT_PS;
    float* diag_s = sm + FEAT_PS + FEAT_QS;
    float* rowmax_s = diag_s + 24;

    int tid = threadIdx.x;
    int which = blockIdx.y;
    const float* src = which ? g_k : g_q;
    float* dstp      = which ? g_kp : g_qp;

    if (tid < 24) rowmax_s[tid] = -INFINITY;

    // load proj (zero-padded to 288 rows), stride 68 (conflict-free for LDS.128)
    for (int i = tid; i < 288 * 17; i += 192) {
        int row = i / 17, c4 = i - row * 17;
        float4 v = make_float4(0.f, 0.f, 0.f, 0.f);
        if (row < NB_ && c4 < 16) v = *(const float4*)(proj + row * 64 + c4 * 4);
        *(float4*)(&ps[row * 68 + c4 * 4]) = v;
    }
    // load 24 rows of q/k
    int rbase24 = blockIdx.x * 24;
    for (int i = tid; i < 24 * 16; i += 192) {
        int row = i >> 4, c4 = i & 15;
        *(float4*)(&qs[row * 64 + c4 * 4]) =
            *(const float4*)(src + (size_t)(rbase24 + row) * 64 + c4 * 4);
    }
    __syncthreads();

    // diag = 0.0625 * sum(x^2)  (dn^2/2 = 1/16)
    if (tid < 24) {
        float s = 0.f;
#pragma unroll
        for (int c = 0; c < 16; c++) {
            float4 v = *(float4*)(&qs[tid * 64 + c * 4]);
            s += v.x * v.x + v.y * v.y + v.z * v.z + v.w * v.w;
        }
        diag_s[tid] = 0.0625f * s;
        if (which) g_kdiag[rbase24 + tid] = 0.0625f * s;
    }

    int w = tid >> 5, lane = tid & 31;
    int rg = (w >= 3) ? 1 : 0;
    int g = w - rg * 3;                 // t-group 0..2
    int rbase = rg * 12;                // local row base

    unsigned long long acc2[12][3];
#pragma unroll
    for (int r = 0; r < 12; r++)
#pragma unroll
        for (int t = 0; t < 3; t++) acc2[r][t] = 0ull;

#pragma unroll 4
    for (int d4 = 0; d4 < 16; d4++) {
        unsigned long long pp[3][2];
#pragma unroll
        for (int t = 0; t < 3; t++) {
            float4 p = *(float4*)(&ps[(lane + (g * 3 + t) * 32) * 68 + d4 * 4]);
            pp[t][0] = pk2(p.x, p.y);
            pp[t][1] = pk2(p.z, p.w);
        }
#pragma unroll
        for (int r = 0; r < 12; r++) {
            float4 q = *(float4*)(&qs[(rbase + r) * 64 + d4 * 4]);
            unsigned long long qa = pk2(q.x, q.y), qb = pk2(q.z, q.w);
#pragma unroll
            for (int t = 0; t < 3; t++) {
                ffma2(acc2[r][t], qa, pp[t][0]);
                ffma2(acc2[r][t], qb, pp[t][1]);
            }
        }
    }

    const float DN = 0.3535533905932738f;      // 64^-0.25
    const float RATIO = 0.06131393394849658f;  // 266^-0.5

    if (which == 0) {
        // per-row partial max over this warp's j-subset -> shared atomic
#pragma unroll
        for (int r = 0; r < 12; r++) {
            float m = -INFINITY;
#pragma unroll
            for (int t = 0; t < 3; t++) {
                int j = lane + (g * 3 + t) * 32;
                float2 u = upk2(acc2[r][t]);
                float v = u.x + u.y;
                if (j < NB_) m = fmaxf(m, v);
            }
#pragma unroll
            for (int o = 16; o; o >>= 1) m = fmaxf(m, __shfl_xor_sync(0xffffffffu, m, o));
            if (lane == 0) atomicMaxF(&rowmax_s[rbase + r], m * DN);
        }
        __syncthreads();
#pragma unroll
        for (int r = 0; r < 12; r++) {
            int rl = rbase + r;
            float c = diag_s[rl] + rowmax_s[rl];
            float* dr = dstp + (size_t)(rbase24 + rl) * NB_;
#pragma unroll
            for (int t = 0; t < 3; t++) {
                int j = lane + (g * 3 + t) * 32;
                if (j < NB_) {
                    float2 u = upk2(acc2[r][t]);
                    dr[j] = RATIO * (expf((u.x + u.y) * DN - c) + EPS_);
                }
            }
        }
    } else {
        // key path: write raw dash (*DN); accumulate per-bh max
        float curmax = -INFINITY;
        int curbh = (rbase24 + rbase) >> 12;
#pragma unroll
        for (int r = 0; r < 12; r++) {
            int row = rbase24 + rbase + r;
            float* dr = dstp + (size_t)row * NB_;
            float m = -INFINITY;
#pragma unroll
            for (int t = 0; t < 3; t++) {
                int j = lane + (g * 3 + t) * 32;
                float2 u = upk2(acc2[r][t]);
                float v = u.x + u.y;
                if (j < NB_) { dr[j] = v * DN; m = fmaxf(m, v); }
            }
#pragma unroll
            for (int o = 16; o; o >>= 1) m = fmaxf(m, __shfl_xor_sync(0xffffffffu, m, o));
            if (lane == 0) {
                int bh = row >> 12;
                if (bh != curbh) {
                    atomicMaxF(&g_kmax[curbh], curmax);
                    curmax = -INFINITY;
                    curbh = bh;
                }
                curmax = fmaxf(curmax, m * DN);
            }
        }
        if (lane == 0) atomicMaxF(&g_kmax[curbh], curmax);
    }
}

// ---------------- K transform: kp = ratio*(exp(dash - diag - m_bh) + eps) ------
__global__ void perf_ktrans_kernel() {
    const float RATIO = 0.06131393394849658f;
    int idx = blockIdx.x * blockDim.x + threadIdx.x;
    const int total2 = R_ * NB_ / 2;
    if (idx >= total2) return;
    float2* p = ((float2*)g_kp) + idx;
    float2 v = *p;
    int e = idx * 2;
    int row = e / NB_;
    float c = g_kdiag[row] + g_kmax[row >> 12];
    v.x = RATIO * (expf(v.x - c) + EPS_);
    v.y = RATIO * (expf(v.y - c) + EPS_);
    *p = v;
}

// ---------------- k_sum (deterministic two-stage) ----------------
__global__ void perf_ksumA_kernel() {
    int bh = blockIdx.y, ch = blockIdx.x, j = threadIdx.x;
    if (j >= NB_) return;
    const float* base = g_kp + ((size_t)(bh * N_ + ch * 128)) * NB_ + j;
    float s = 0.f;
#pragma unroll 4
    for (int r = 0; r < 128; r++) s += base[(size_t)r * NB_];
    g_ksum_part[(bh * 32 + ch) * NB_ + j] = s;
}

__global__ void perf_ksumB_kernel() {
    int bh = blockIdx.x, j = threadIdx.x;
    if (j >= NB_) return;
    float s = 0.f;
#pragma unroll
    for (int c = 0; c < 32; c++) s += g_ksum_part[(bh * 32 + c) * NB_ + j];
    g_ksum[bh * NB_ + j] = s;
}

// ---------------- ctx = kp^T v  (k-split tiled GEMM, f32x2) ----------------
__global__ __launch_bounds__(256)
void perf_ctx_kernel() {
    __shared__ float kt[16][68];
    __shared__ float vt[16][68];
    int jt = blockIdx.x, ks = blockIdx.y, bh = blockIdx.z;
    int j0 = jt * 64, n0 = ks * 1024;
    int tid = threadIdx.x, tx = tid & 15, ty = tid >> 4;
    const float* kbase = g_kp + (size_t)bh * N_ * NB_;
    const float* vbase = g_v + (size_t)bh * N_ * DH_;

    unsigned long long acc2[4][2];
#pragma unroll
    for (int a = 0; a < 4; a++) { acc2[a][0] = 0ull; acc2[a][1] = 0ull; }

    for (int nn = 0; nn < 1024; nn += 16) {
#pragma unroll
        for (int i = 0; i < 2; i++) {
            int id = i * 256 + tid;
            int r = id >> 5, c2 = id & 31;
            int j = j0 + c2 * 2;
            float2 v = make_float2(0.f, 0.f);
            if (j + 1 < NB_)
                v = *(const float2*)(kbase + (size_t)(n0 + nn + r) * NB_ + j);
            kt[r][c2 * 2] = v.x;
            kt[r][c2 * 2 + 1] = v.y;
        }
        {
            int r = tid >> 4, c4 = tid & 15;
            float4 v = *(const float4*)(vbase + (size_t)(n0 + nn + r) * DH_ + c4 * 4);
            *(float4*)(&vt[r][c4 * 4]) = v;
        }
        __syncthreads();
#pragma unroll
        for (int k = 0; k < 16; k++) {
            float4 a = *(float4*)(&kt[k][ty * 4]);
            float4 b = *(float4*)(&vt[k][tx * 4]);
            unsigned long long b01 = pk2(b.x, b.y);
            unsigned long long b23 = pk2(b.z, b.w);
            float av[4] = {a.x, a.y, a.z, a.w};
#pragma unroll
            for (int i = 0; i < 4; i++) {
                unsigned long long ad = pk2(av[i], av[i]);
                ffma2(acc2[i][0], ad, b01);
                ffma2(acc2[i][1], ad, b23);
            }
        }
        __syncthreads();
    }

    float* obase = g_ctx_part + (size_t)(ks * BH_ + bh) * NB_ * DH_;
#pragma unroll
    for (int jj = 0; jj < 4; jj++) {
        int j = j0 + ty * 4 + jj;
        if (j < NB_) {
            float2 p0 = upk2(acc2[jj][0]);
            float2 p1 = upk2(acc2[jj][1]);
            *(float4*)(&obase[(size_t)j * DH_ + tx * 4]) =
                make_float4(p0.x, p0.y, p1.x, p1.y);
        }
    }
}

__global__ void perf_ctxred_kernel() {
    const int T = BH_ * NB_ * DH_;
    int i = blockIdx.x * blockDim.x + threadIdx.x;
    if (i >= T) return;
    g_ctx[i] = g_ctx_part[i] + g_ctx_part[i + T] + g_ctx_part[i + 2 * T] + g_ctx_part[i + 3 * T];
}

// ---------------- out = (qp @ ctx) / (qp @ ksum), 8-row blocked, f32x2 --------
// Block: 512 threads = 16 warps, covers 256 rows (warp: 16 rows in 2 groups of 8)
// smem floats: ctx 266*64 | ksum 268 | qs 16 warps x 8 rows x 272
#define OUT_QS_W (8 * 272)
#define OUT_SMEM ((NB_ * DH_ + 268 + 16 * OUT_QS_W) * 4)

__global__ __launch_bounds__(512)
void perf_out_kernel(float* __restrict__ out) {
    extern __shared__ float sm[];
    float* ctx_s = sm;
    float* ksum_s = sm + NB_ * DH_;
    float* qsall = sm + NB_ * DH_ + 268;
    int tid = threadIdx.x, w = tid >> 5, lane = tid & 31;
    int row0 = blockIdx.x * 256;
    int bh = row0 >> 12;

    const float* cb = g_ctx + (size_t)bh * NB_ * DH_;
    for (int i = tid; i < NB_ * DH_ / 4; i += 512)
        *(float4*)(&ctx_s[i * 4]) = *(const float4*)(cb + i * 4);
    for (int i = tid; i < NB_; i += 512) ksum_s[i] = g_ksum[bh * NB_ + i];
    __syncthreads();

    int bb = bh / H_, h = bh - bb * H_;
    float* qs = qsall + w * OUT_QS_W;

    for (int grp = 0; grp < 2; grp++) {
        int rowg = row0 + w * 16 + grp * 8;

        // fill qp for 8 rows
        __syncwarp();
#pragma unroll
        for (int r = 0; r < 8; r++) {
            const float2* qr = (const float2*)(g_qp + (size_t)(rowg + r) * NB_);
#pragma unroll
            for (int k = 0; k < 5; k++) {
                int idx = lane + 32 * k;
                if (idx < NB_ / 2) {
                    float2 v = qr[idx];
                    qs[r * 272 + idx * 2] = v.x;
                    qs[r * 272 + idx * 2 + 1] = v.y;
                }
            }
        }
        __syncwarp();

        // denominators
        float dinv[8];
#pragma unroll
        for (int r = 0; r < 8; r++) {
            float s = 0.f;
#pragma unroll
            for (int t = 0; t < 9; t++) {
                int j = lane + 32 * t;
                if (j < NB_) s += qs[r * 272 + j] * ksum_s[j];
            }
#pragma unroll
            for (int o = 16; o; o >>= 1) s += __shfl_xor_sync(0xffffffffu, s, o);
            dinv[r] = 1.0f / s;
        }

        unsigned long long acc2[8];
#pragma unroll
        for (int r = 0; r < 8; r++) acc2[r] = 0ull;

        for (int j0 = 0; j0 < 264; j0 += 4) {
            float qv[8][4];
#pragma unroll
            for (int r = 0; r < 8; r++)
                *(float4*)qv[r] = *(float4*)(&qs[r * 272 + j0]);
#pragma unroll
            for (int jj = 0; jj < 4; jj++) {
                unsigned long long c = *(const unsigned long long*)(&ctx_s[(j0 + jj) * 64 + 2 * lane]);
#pragma unroll
                for (int r = 0; r < 8; r++) {
                    unsigned long long ad = pk2(qv[r][jj], qv[r][jj]);
                    ffma2(acc2[r], ad, c);
                }
            }
        }
#pragma unroll
        for (int jj = 264; jj < NB_; jj++) {
            unsigned long long c = *(const unsigned long long*)(&ctx_s[jj * 64 + 2 * lane]);
#pragma unroll
            for (int r = 0; r < 8; r++) {
                float qv = qs[r * 272 + jj];
                unsigned long long ad = pk2(qv, qv);
                ffma2(acc2[r], ad, c);
            }
        }

#pragma unroll
        for (int r = 0; r < 8; r++) {
            int row = rowg + r;
            int n = row & (N_ - 1);
            float2 u = upk2(acc2[r]);
            *(float2*)(out + ((size_t)(bb * N_ + n)) * 768 + h * 64 + 2 * lane) =
                make_float2(u.x * dinv[r], u.y * dinv[r]);
        }
    }
}

// ---------------- launch ----------------
extern "C" void kernel_launch(void* const* d_in, const int* in_sizes, int n_in,
                              void* d_out, int out_size) {
    (void)in_sizes; (void)n_in; (void)out_size;
    const float* hs   = (const float*)d_in[0];
    const float* Wq   = (const float*)d_in[1];
    const float* bq   = (const float*)d_in[2];
    const float* Wk   = (const float*)d_in[3];
    const float* bk   = (const float*)d_in[4];
    const float* Wv   = (const float*)d_in[5];
    const float* bv   = (const float*)d_in[6];
    const float* proj = (const float*)d_in[7];
    float* out = (float*)d_out;

    cudaFuncSetAttribute(perf_feat_kernel, cudaFuncAttributeMaxDynamicSharedMemorySize, FEAT_SMEM);
    cudaFuncSetAttribute(perf_out_kernel,  cudaFuncAttributeMaxDynamicSharedMemorySize, OUT_SMEM);

    perf_init_kernel<<<1, 64>>>();
    perf_qkv_gemm<<<dim3(128, 6, 3), 256>>>(hs, Wq, bq, Wk, bk, Wv, bv);
    perf_feat_kernel<<<dim3(R_ / 24, 2), 192, FEAT_SMEM>>>(proj);
    perf_ktrans_kernel<<<(R_ * NB_ / 2) / 256, 256>>>();
    perf_ksumA_kernel<<<dim3(32, BH_), 288>>>();
    perf_ksumB_kernel<<<BH_, 288>>>();
    perf_ctx_kernel<<<dim3(5, 4, BH_), 256>>>();
    perf_ctxred_kernel<<<(BH_ * NB_ * DH_ + 255) / 256, 256>>>();
    perf_out_kernel<<<R_ / 256, 512, OUT_SMEM>>>(out);
}

// round 13
// speedup vs baseline: 1.9954x; 1.3814x over previous
#include <cuda_runtime.h>
#include <cuda_bf16.h>
#include <math.h>

#define B_   4
#define N_   4096
#define H_   12
#define DH_  64
#define NB_  266
#define BH_  (B_*H_)           // 48
#define R_   (B_*H_*N_)        // 196608
#define EPS_ 1e-4f

// ---------------- scratch (static device memory; no allocation) ----------------
__device__ float g_q[R_ * DH_];
__device__ float g_k[R_ * DH_];
__device__ float g_v[R_ * DH_];
__device__ float g_qp[R_ * NB_];
__device__ float g_kp[R_ * NB_];           // raw dash, then exp in place
__device__ float g_kdiag[R_];
__device__ float g_kmax[BH_];
__device__ float g_ksum_part[BH_ * 32 * NB_];
__device__ float g_ksum[BH_ * NB_];
__device__ float g_ctx_part[4 * BH_ * NB_ * DH_];
__device__ float g_ctx[BH_ * NB_ * DH_];
// bf16 hi/lo split operands for tensor-core QKV
__device__ __nv_bfloat16 g_ahi[16384 * 768];
__device__ __nv_bfloat16 g_alo[16384 * 768];
__device__ __nv_bfloat16 g_whi[2304 * 768];
__device__ __nv_bfloat16 g_wlo[2304 * 768];

// ---------------- helpers ----------------
static __device__ __forceinline__ unsigned long long pk2(float lo, float hi) {
    unsigned long long r;
    asm("mov.b64 %0, {%1, %2};" : "=l"(r) : "f"(lo), "f"(hi));
    return r;
}
static __device__ __forceinline__ float2 upk2(unsigned long long v) {
    float2 r;
    asm("mov.b64 {%0, %1}, %2;" : "=f"(r.x), "=f"(r.y) : "l"(v));
    return r;
}
static __device__ __forceinline__ void ffma2(unsigned long long& d,
                                             unsigned long long a,
                                             unsigned long long b) {
    asm("fma.rn.f32x2 %0, %1, %2, %0;" : "+l"(d) : "l"(a), "l"(b));
}
static __device__ __forceinline__ void atomicMaxF(float* addr, float v) {
    if (v >= 0.f) atomicMax((int*)addr, __float_as_int(v));
    else          atomicMin((unsigned int*)addr, __float_as_uint(v));
}
static __device__ __forceinline__ unsigned smem_u32(const void* p) {
    unsigned a;
    asm("{ .reg .u64 t; cvta.to.shared.u64 t, %1; cvt.u32.u64 %0, t; }" : "=r"(a) : "l"(p));
    return a;
}

static __device__ __forceinline__ void ldmx4(unsigned& r0, unsigned& r1,
                                             unsigned& r2, unsigned& r3, unsigned a) {
    asm volatile("ldmatrix.sync.aligned.m8n8.x4.shared.b16 {%0,%1,%2,%3}, [%4];"
                 : "=r"(r0), "=r"(r1), "=r"(r2), "=r"(r3) : "r"(a));
}
static __device__ __forceinline__ void ldmx2(unsigned& r0, unsigned& r1, unsigned a) {
    asm volatile("ldmatrix.sync.aligned.m8n8.x2.shared.b16 {%0,%1}, [%2];"
                 : "=r"(r0), "=r"(r1) : "r"(a));
}
static __device__ __forceinline__ void mma16816(float* c, const unsigned* a,
                                                const unsigned* b) {
    asm volatile(
        "mma.sync.aligned.m16n8k16.row.col.f32.bf16.bf16.f32 "
        "{%0,%1,%2,%3}, {%4,%5,%6,%7}, {%8,%9}, {%0,%1,%2,%3};"
        : "+f"(c[0]), "+f"(c[1]), "+f"(c[2]), "+f"(c[3])
        : "r"(a[0]), "r"(a[1]), "r"(a[2]), "r"(a[3]), "r"(b[0]), "r"(b[1]));
}

__global__ void perf_init_kernel() {
    if (threadIdx.x < BH_) g_kmax[threadIdx.x] = -INFINITY;
}

// ---------------- hi/lo bf16 split of activations & weights ----------------
__global__ __launch_bounds__(256)
void perf_cvt_a(const float* __restrict__ hs) {
    int i = blockIdx.x * blockDim.x + threadIdx.x;      // float4 index
    const int T4 = 16384 * 768 / 4;
    if (i >= T4) return;
    float4 v = ((const float4*)hs)[i];
    __nv_bfloat16 hx = __float2bfloat16_rn(v.x), hy = __float2bfloat16_rn(v.y);
    __nv_bfloat16 hz = __float2bfloat16_rn(v.z), hw = __float2bfloat16_rn(v.w);
    __nv_bfloat162* ph = (__nv_bfloat162*)(g_ahi + i * 4);
    ph[0] = __nv_bfloat162(hx, hy);
    ph[1] = __nv_bfloat162(hz, hw);
    __nv_bfloat162* pl = (__nv_bfloat162*)(g_alo + i * 4);
    pl[0] = __nv_bfloat162(__float2bfloat16_rn(v.x - __bfloat162float(hx)),
                           __float2bfloat16_rn(v.y - __bfloat162float(hy)));
    pl[1] = __nv_bfloat162(__float2bfloat16_rn(v.z - __bfloat162float(hz)),
                           __float2bfloat16_rn(v.w - __bfloat162float(hw)));
}

__global__ __launch_bounds__(256)
void perf_cvt_w(const float* __restrict__ Wq, const float* __restrict__ Wk,
                const float* __restrict__ Wv) {
    int i = blockIdx.x * blockDim.x + threadIdx.x;      // float4 index
    const int T4 = 2304 * 768 / 4;
    if (i >= T4) return;
    int e = i * 4;
    int row = e / 768, col = e - row * 768;
    int z = row / 768;
    const float* W = (z == 0) ? Wq : (z == 1) ? Wk : Wv;
    float4 v = *(const float4*)(W + (size_t)(row - z * 768) * 768 + col);
    __nv_bfloat16 hx = __float2bfloat16_rn(v.x), hy = __float2bfloat16_rn(v.y);
    __nv_bfloat16 hz = __float2bfloat16_rn(v.z), hw = __float2bfloat16_rn(v.w);
    __nv_bfloat162* ph = (__nv_bfloat162*)(g_whi + e);
    ph[0] = __nv_bfloat162(hx, hy);
    ph[1] = __nv_bfloat162(hz, hw);
    __nv_bfloat162* pl = (__nv_bfloat162*)(g_wlo + e);
    pl[0] = __nv_bfloat162(__float2bfloat16_rn(v.x - __bfloat162float(hx)),
                           __float2bfloat16_rn(v.y - __bfloat162float(hy)));
    pl[1] = __nv_bfloat162(__float2bfloat16_rn(v.z - __bfloat162float(hz)),
                           __float2bfloat16_rn(v.w - __bfloat162float(hw)));
}

// ---------------- QKV GEMM on mma.sync HMMA (bf16 hi/lo, 3-MMA split) ---------
// C[16384, 2304] = A[16384,768] x W[2304,768]^T.
// Block tile M=128, N=128, K-chunk 32. 8 warps (2 m x 4 n), warp tile 64x32.
// smem rows padded to 80 B (bank-step 20 -> ldmatrix conflict-free).
#define QROW 80
#define OFF_AH 0
#define OFF_AL (128 * QROW)
#define OFF_BH (2 * 128 * QROW)
#define OFF_BL (3 * 128 * QROW)

__global__ __launch_bounds__(256)
void perf_qkv_mma(const float* __restrict__ bq, const float* __restrict__ bk,
                  const float* __restrict__ bv) {
    __shared__ __align__(16) unsigned char smc[4 * 128 * QROW];
    __shared__ float bias_s[128];
    unsigned sb = smem_u32(smc);

    int tid = threadIdx.x, wid = tid >> 5, lane = tid & 31;
    int warp_m = wid & 1, warp_n = wid >> 1;
    int m0 = blockIdx.x * 128;
    int n0 = blockIdx.y * 128;           // row in concatenated W [2304]
    int z = blockIdx.y / 6;              // 0=q, 1=k, 2=v
    int o_base = (blockIdx.y - z * 6) * 128;
    const float* bias = (z == 0) ? bq : (z == 1) ? bk : bv;
    float* dst = (z == 0) ? g_q : (z == 1) ? g_k : g_v;
    if (tid < 128) bias_s[tid] = bias[o_base + tid];

    float acc[4][4][4];
#pragma unroll
    for (int mt = 0; mt < 4; mt++)
#pragma unroll
        for (int nt = 0; nt < 4; nt++)
#pragma unroll
            for (int e = 0; e < 4; e++) acc[mt][nt][e] = 0.f;

    int r = tid >> 1, half = tid & 1;

    for (int ch = 0; ch < 24; ch++) {
        int k0 = ch * 32;
        {
            // each thread fills 32 bytes (16 bf16) per buffer: full 64-byte rows
            size_t goA = (size_t)(m0 + r) * 768 + k0 + half * 16;
            size_t goB = (size_t)(n0 + r) * 768 + k0 + half * 16;
            unsigned so = (unsigned)(r * QROW + half * 32);
            const uint4* pAh = (const uint4*)(g_ahi + goA);
            const uint4* pAl = (const uint4*)(g_alo + goA);
            const uint4* pBh = (const uint4*)(g_whi + goB);
            const uint4* pBl = (const uint4*)(g_wlo + goB);
            *(uint4*)(smc + OFF_AH + so)      = pAh[0];
            *(uint4*)(smc + OFF_AH + so + 16) = pAh[1];
            *(uint4*)(smc + OFF_AL + so)      = pAl[0];
            *(uint4*)(smc + OFF_AL + so + 16) = pAl[1];
            *(uint4*)(smc + OFF_BH + so)      = pBh[0];
            *(uint4*)(smc + OFF_BH + so + 16) = pBh[1];
            *(uint4*)(smc + OFF_BL + so)      = pBl[0];
            *(uint4*)(smc + OFF_BL + so + 16) = pBl[1];
        }
        __syncthreads();

#pragma unroll
        for (int ks = 0; ks < 2; ks++) {
            unsigned ah[4][4], al[4][4];
#pragma unroll
            for (int mt = 0; mt < 4; mt++) {
                unsigned ra = (unsigned)((warp_m * 64 + mt * 16 + (lane & 15)) * QROW +
                                         ks * 32 + (lane >> 4) * 16);
                ldmx4(ah[mt][0], ah[mt][1], ah[mt][2], ah[mt][3], sb + OFF_AH + ra);
                ldmx4(al[mt][0], al[mt][1], al[mt][2], al[mt][3], sb + OFF_AL + ra);
            }
#pragma unroll
            for (int nt = 0; nt < 4; nt++) {
                unsigned rb = (unsigned)((warp_n * 32 + nt * 8 + (lane & 7)) * QROW +
                                         ks * 32 + ((lane >> 3) & 1) * 16);
                unsigned bh[2], bl[2];
                ldmx2(bh[0], bh[1], sb + OFF_BH + rb);
                ldmx2(bl[0], bl[1], sb + OFF_BL + rb);
#pragma unroll
                for (int mt = 0; mt < 4; mt++) {
                    mma16816(acc[mt][nt], ah[mt], bh);
                    mma16816(acc[mt][nt], ah[mt], bl);
                    mma16816(acc[mt][nt], al[mt], bh);
                }
            }
        }
        __syncthreads();
    }

    // epilogue: add bias, store to [b,h,n,d]
#pragma unroll
    for (int mt = 0; mt < 4; mt++) {
#pragma unroll
        for (int nt = 0; nt < 4; nt++) {
            int cb = warp_n * 32 + nt * 8 + (lane & 3) * 2;   // col within block
            int oc = o_base + cb;
            int h = oc >> 6, d = oc & 63;
            float bx = bias_s[cb], by = bias_s[cb + 1];
#pragma unroll
            for (int hh = 0; hh < 2; hh++) {
                int gi = m0 + warp_m * 64 + mt * 16 + (lane >> 2) + hh * 8;
                int bbi = gi >> 12, nn = gi & (N_ - 1);
                float2 v = make_float2(acc[mt][nt][hh * 2 + 0] + bx,
                                       acc[mt][nt][hh * 2 + 1] + by);
                *(float2*)(dst + ((size_t)(bbi * H_ + h) * N_ + nn) * DH_ + d) = v;
            }
        }
    }
}

// ---------------- FAVOR+ feature map (12-row x 3-tgroup blocked, f32x2) --------
#define FEAT_PS   (288 * 68)
#define FEAT_QS   (24 * 64)
#define FEAT_SMEM ((FEAT_PS + FEAT_QS + 24 + 24) * 4)

__global__ __launch_bounds__(192)
void perf_feat_kernel(const float* __restrict__ proj) {
    extern __shared__ float sm[];
    float* ps = sm;
    float* qs = sm + FEAT_PS;
    float* diag_s = sm + FEAT_PS + FEAT_QS;
    float* rowmax_s = diag_s + 24;

    int tid = threadIdx.x;
    int which = blockIdx.y;
    const float* src = which ? g_k : g_q;
    float* dstp      = which ? g_kp : g_qp;

    if (tid < 24) rowmax_s[tid] = -INFINITY;

    for (int i = tid; i < 288 * 17; i += 192) {
        int row = i / 17, c4 = i - row * 17;
        float4 v = make_float4(0.f, 0.f, 0.f, 0.f);
        if (row < NB_ && c4 < 16) v = *(const float4*)(proj + row * 64 + c4 * 4);
        *(float4*)(&ps[row * 68 + c4 * 4]) = v;
    }
    int rbase24 = blockIdx.x * 24;
    for (int i = tid; i < 24 * 16; i += 192) {
        int row = i >> 4, c4 = i & 15;
        *(float4*)(&qs[row * 64 + c4 * 4]) =
            *(const float4*)(src + (size_t)(rbase24 + row) * 64 + c4 * 4);
    }
    __syncthreads();

    if (tid < 24) {
        float s = 0.f;
#pragma unroll
        for (int c = 0; c < 16; c++) {
            float4 v = *(float4*)(&qs[tid * 64 + c * 4]);
            s += v.x * v.x + v.y * v.y + v.z * v.z + v.w * v.w;
        }
        diag_s[tid] = 0.0625f * s;
        if (which) g_kdiag[rbase24 + tid] = 0.0625f * s;
    }

    int w = tid >> 5, lane = tid & 31;
    int rg = (w >= 3) ? 1 : 0;
    int g = w - rg * 3;
    int rbase = rg * 12;

    unsigned long long acc2[12][3];
#pragma unroll
    for (int r = 0; r < 12; r++)
#pragma unroll
        for (int t = 0; t < 3; t++) acc2[r][t] = 0ull;

#pragma unroll 4
    for (int d4 = 0; d4 < 16; d4++) {
        unsigned long long pp[3][2];
#pragma unroll
        for (int t = 0; t < 3; t++) {
            float4 p = *(float4*)(&ps[(lane + (g * 3 + t) * 32) * 68 + d4 * 4]);
            pp[t][0] = pk2(p.x, p.y);
            pp[t][1] = pk2(p.z, p.w);
        }
#pragma unroll
        for (int r = 0; r < 12; r++) {
            float4 q = *(float4*)(&qs[(rbase + r) * 64 + d4 * 4]);
            unsigned long long qa = pk2(q.x, q.y), qb = pk2(q.z, q.w);
#pragma unroll
            for (int t = 0; t < 3; t++) {
                ffma2(acc2[r][t], qa, pp[t][0]);
                ffma2(acc2[r][t], qb, pp[t][1]);
            }
        }
    }

    const float DN = 0.3535533905932738f;
    const float RATIO = 0.06131393394849658f;

    if (which == 0) {
#pragma unroll
        for (int r = 0; r < 12; r++) {
            float m = -INFINITY;
#pragma unroll
            for (int t = 0; t < 3; t++) {
                int j = lane + (g * 3 + t) * 32;
                float2 u = upk2(acc2[r][t]);
                float v = u.x + u.y;
                if (j < NB_) m = fmaxf(m, v);
            }
#pragma unroll
            for (int o = 16; o; o >>= 1) m = fmaxf(m, __shfl_xor_sync(0xffffffffu, m, o));
            if (lane == 0) atomicMaxF(&rowmax_s[rbase + r], m * DN);
        }
        __syncthreads();
#pragma unroll
        for (int r = 0; r < 12; r++) {
            int rl = rbase + r;
            float c = diag_s[rl] + rowmax_s[rl];
            float* dr = dstp + (size_t)(rbase24 + rl) * NB_;
#pragma unroll
            for (int t = 0; t < 3; t++) {
                int j = lane + (g * 3 + t) * 32;
                if (j < NB_) {
                    float2 u = upk2(acc2[r][t]);
                    dr[j] = RATIO * (expf((u.x + u.y) * DN - c) + EPS_);
                }
            }
        }
    } else {
        float curmax = -INFINITY;
        int curbh = (rbase24 + rbase) >> 12;
#pragma unroll
        for (int r = 0; r < 12; r++) {
            int row = rbase24 + rbase + r;
            float* dr = dstp + (size_t)row * NB_;
            float m = -INFINITY;
#pragma unroll
            for (int t = 0; t < 3; t++) {
                int j = lane + (g * 3 + t) * 32;
                float2 u = upk2(acc2[r][t]);
                float v = u.x + u.y;
                if (j < NB_) { dr[j] = v * DN; m = fmaxf(m, v); }
            }
#pragma unroll
            for (int o = 16; o; o >>= 1) m = fmaxf(m, __shfl_xor_sync(0xffffffffu, m, o));
            if (lane == 0) {
                int bh = row >> 12;
                if (bh != curbh) {
                    atomicMaxF(&g_kmax[curbh], curmax);
                    curmax = -INFINITY;
                    curbh = bh;
                }
                curmax = fmaxf(curmax, m * DN);
            }
        }
        if (lane == 0) atomicMaxF(&g_kmax[curbh], curmax);
    }
}

// ---------------- K transform ----------------
__global__ void perf_ktrans_kernel() {
    const float RATIO = 0.06131393394849658f;
    int idx = blockIdx.x * blockDim.x + threadIdx.x;
    const int total2 = R_ * NB_ / 2;
    if (idx >= total2) return;
    float2* p = ((float2*)g_kp) + idx;
    float2 v = *p;
    int e = idx * 2;
    int row = e / NB_;
    float c = g_kdiag[row] + g_kmax[row >> 12];
    v.x = RATIO * (expf(v.x - c) + EPS_);
    v.y = RATIO * (expf(v.y - c) + EPS_);
    *p = v;
}

// ---------------- k_sum ----------------
__global__ void perf_ksumA_kernel() {
    int bh = blockIdx.y, ch = blockIdx.x, j = threadIdx.x;
    if (j >= NB_) return;
    const float* base = g_kp + ((size_t)(bh * N_ + ch * 128)) * NB_ + j;
    float s = 0.f;
#pragma unroll 4
    for (int r = 0; r < 128; r++) s += base[(size_t)r * NB_];
    g_ksum_part[(bh * 32 + ch) * NB_ + j] = s;
}

__global__ void perf_ksumB_kernel() {
    int bh = blockIdx.x, j = threadIdx.x;
    if (j >= NB_) return;
    float s = 0.f;
#pragma unroll
    for (int c = 0; c < 32; c++) s += g_ksum_part[(bh * 32 + c) * NB_ + j];
    g_ksum[bh * NB_ + j] = s;
}

// ---------------- ctx = kp^T v ----------------
__global__ __launch_bounds__(256)
void perf_ctx_kernel() {
    __shared__ float kt[16][68];
    __shared__ float vt[16][68];
    int jt = blockIdx.x, ks = blockIdx.y, bh = blockIdx.z;
    int j0 = jt * 64, n0 = ks * 1024;
    int tid = threadIdx.x, tx = tid & 15, ty = tid >> 4;
    const float* kbase = g_kp + (size_t)bh * N_ * NB_;
    const float* vbase = g_v + (size_t)bh * N_ * DH_;

    unsigned long long acc2[4][2];
#pragma unroll
    for (int a = 0; a < 4; a++) { acc2[a][0] = 0ull; acc2[a][1] = 0ull; }

    for (int nn = 0; nn < 1024; nn += 16) {
#pragma unroll
        for (int i = 0; i < 2; i++) {
            int id = i * 256 + tid;
            int r = id >> 5, c2 = id & 31;
            int j = j0 + c2 * 2;
            float2 v = make_float2(0.f, 0.f);
            if (j + 1 < NB_)
                v = *(const float2*)(kbase + (size_t)(n0 + nn + r) * NB_ + j);
            kt[r][c2 * 2] = v.x;
            kt[r][c2 * 2 + 1] = v.y;
        }
        {
            int r = tid >> 4, c4 = tid & 15;
            float4 v = *(const float4*)(vbase + (size_t)(n0 + nn + r) * DH_ + c4 * 4);
            *(float4*)(&vt[r][c4 * 4]) = v;
        }
        __syncthreads();
#pragma unroll
        for (int k = 0; k < 16; k++) {
            float4 a = *(float4*)(&kt[k][ty * 4]);
            float4 b = *(float4*)(&vt[k][tx * 4]);
            unsigned long long b01 = pk2(b.x, b.y);
            unsigned long long b23 = pk2(b.z, b.w);
            float av[4] = {a.x, a.y, a.z, a.w};
#pragma unroll
            for (int i = 0; i < 4; i++) {
                unsigned long long ad = pk2(av[i], av[i]);
                ffma2(acc2[i][0], ad, b01);
                ffma2(acc2[i][1], ad, b23);
            }
        }
        __syncthreads();
    }

    float* obase = g_ctx_part + (size_t)(ks * BH_ + bh) * NB_ * DH_;
#pragma unroll
    for (int jj = 0; jj < 4; jj++) {
        int j = j0 + ty * 4 + jj;
        if (j < NB_) {
            float2 p0 = upk2(acc2[jj][0]);
            float2 p1 = upk2(acc2[jj][1]);
            *(float4*)(&obase[(size_t)j * DH_ + tx * 4]) =
                make_float4(p0.x, p0.y, p1.x, p1.y);
        }
    }
}

__global__ void perf_ctxred_kernel() {
    const int T = BH_ * NB_ * DH_;
    int i = blockIdx.x * blockDim.x + threadIdx.x;
    if (i >= T) return;
    g_ctx[i] = g_ctx_part[i] + g_ctx_part[i + T] + g_ctx_part[i + 2 * T] + g_ctx_part[i + 3 * T];
}

// ---------------- out = (qp @ ctx) / (qp @ ksum) ----------------
#define OUT_QS_W (8 * 272)
#define OUT_SMEM ((NB_ * DH_ + 268 + 16 * OUT_QS_W) * 4)

__global__ __launch_bounds__(512)
void perf_out_kernel(float* __restrict__ out) {
    extern __shared__ float sm[];
    float* ctx_s = sm;
    float* ksum_s = sm + NB_ * DH_;
    float* qsall = sm + NB_ * DH_ + 268;
    int tid = threadIdx.x, w = tid >> 5, lane = tid & 31;
    int row0 = blockIdx.x * 256;
    int bh = row0 >> 12;

    const float* cb = g_ctx + (size_t)bh * NB_ * DH_;
    for (int i = tid; i < NB_ * DH_ / 4; i += 512)
        *(float4*)(&ctx_s[i * 4]) = *(const float4*)(cb + i * 4);
    for (int i = tid; i < NB_; i += 512) ksum_s[i] = g_ksum[bh * NB_ + i];
    __syncthreads();

    int bb = bh / H_, h = bh - bb * H_;
    float* qs = qsall + w * OUT_QS_W;

    for (int grp = 0; grp < 2; grp++) {
        int rowg = row0 + w * 16 + grp * 8;

        __syncwarp();
#pragma unroll
        for (int r = 0; r < 8; r++) {
            const float2* qr = (const float2*)(g_qp + (size_t)(rowg + r) * NB_);
#pragma unroll
            for (int k = 0; k < 5; k++) {
                int idx = lane + 32 * k;
                if (idx < NB_ / 2) {
                    float2 v = qr[idx];
                    qs[r * 272 + idx * 2] = v.x;
                    qs[r * 272 + idx * 2 + 1] = v.y;
                }
            }
        }
        __syncwarp();

        float dinv[8];
#pragma unroll
        for (int r = 0; r < 8; r++) {
            float s = 0.f;
#pragma unroll
            for (int t = 0; t < 9; t++) {
                int j = lane + 32 * t;
                if (j < NB_) s += qs[r * 272 + j] * ksum_s[j];
            }
#pragma unroll
            for (int o = 16; o; o >>= 1) s += __shfl_xor_sync(0xffffffffu, s, o);
            dinv[r] = 1.0f / s;
        }

        unsigned long long acc2[8];
#pragma unroll
        for (int r = 0; r < 8; r++) acc2[r] = 0ull;

        for (int j0 = 0; j0 < 264; j0 += 4) {
            float qv[8][4];
#pragma unroll
            for (int r = 0; r < 8; r++)
                *(float4*)qv[r] = *(float4*)(&qs[r * 272 + j0]);
#pragma unroll
            for (int jj = 0; jj < 4; jj++) {
                unsigned long long c = *(const unsigned long long*)(&ctx_s[(j0 + jj) * 64 + 2 * lane]);
#pragma unroll
                for (int r = 0; r < 8; r++) {
                    unsigned long long ad = pk2(qv[r][jj], qv[r][jj]);
                    ffma2(acc2[r], ad, c);
                }
            }
        }
#pragma unroll
        for (int jj = 264; jj < NB_; jj++) {
            unsigned long long c = *(const unsigned long long*)(&ctx_s[jj * 64 + 2 * lane]);
#pragma unroll
            for (int r = 0; r < 8; r++) {
                float qv = qs[r * 272 + jj];
                unsigned long long ad = pk2(qv, qv);
                ffma2(acc2[r], ad, c);
            }
        }

#pragma unroll
        for (int r = 0; r < 8; r++) {
            int row = rowg + r;
            int n = row & (N_ - 1);
            float2 u = upk2(acc2[r]);
            *(float2*)(out + ((size_t)(bb * N_ + n)) * 768 + h * 64 + 2 * lane) =
                make_float2(u.x * dinv[r], u.y * dinv[r]);
        }
    }
}

// ---------------- launch ----------------
extern "C" void kernel_launch(void* const* d_in, const int* in_sizes, int n_in,
                              void* d_out, int out_size) {
    (void)in_sizes; (void)n_in; (void)out_size;
    const float* hs   = (const float*)d_in[0];
    const float* Wq   = (const float*)d_in[1];
    const float* bq   = (const float*)d_in[2];
    const float* Wk   = (const float*)d_in[3];
    const float* bk   = (const float*)d_in[4];
    const float* Wv   = (const float*)d_in[5];
    const float* bv   = (const float*)d_in[6];
    const float* proj = (const float*)d_in[7];
    float* out = (float*)d_out;

    cudaFuncSetAttribute(perf_feat_kernel, cudaFuncAttributeMaxDynamicSharedMemorySize, FEAT_SMEM);
    cudaFuncSetAttribute(perf_out_kernel,  cudaFuncAttributeMaxDynamicSharedMemorySize, OUT_SMEM);

    perf_init_kernel<<<1, 64>>>();
    perf_cvt_a<<<(16384 * 768 / 4 + 255) / 256, 256>>>(hs);
    perf_cvt_w<<<(2304 * 768 / 4 + 255) / 256, 256>>>(Wq, Wk, Wv);
    perf_qkv_mma<<<dim3(128, 18), 256>>>(bq, bk, bv);
    perf_feat_kernel<<<dim3(R_ / 24, 2), 192, FEAT_SMEM>>>(proj);
    perf_ktrans_kernel<<<(R_ * NB_ / 2) / 256, 256>>>();
    perf_ksumA_kernel<<<dim3(32, BH_), 288>>>();
    perf_ksumB_kernel<<<BH_, 288>>>();
    perf_ctx_kernel<<<dim3(5, 4, BH_), 256>>>();
    perf_ctxred_kernel<<<(BH_ * NB_ * DH_ + 255) / 256, 256>>>();
    perf_out_kernel<<<R_ / 256, 512, OUT_SMEM>>>(out);
}

// round 14
// speedup vs baseline: 2.1704x; 1.0877x over previous
#include <cuda_runtime.h>
#include <cuda_bf16.h>
#include <math.h>

#define B_   4
#define N_   4096
#define H_   12
#define DH_  64
#define NB_  266
#define BH_  (B_*H_)           // 48
#define R_   (B_*H_*N_)        // 196608
#define EPS_ 1e-4f

// ---------------- scratch (static device memory; no allocation) ----------------
__device__ float g_q[R_ * DH_];
__device__ float g_k[R_ * DH_];
__device__ float g_v[R_ * DH_];
__device__ float g_qp[R_ * NB_];
__device__ float g_kp[R_ * NB_];           // raw dash (never transformed in place)
__device__ float g_kdiag[R_];
__device__ float g_kmax[BH_];
__device__ float g_ksum_part[BH_ * 32 * NB_];
__device__ float g_ksum[BH_ * NB_];
__device__ float g_ctx_part[4 * BH_ * NB_ * DH_];
__device__ float g_ctx[BH_ * NB_ * DH_];
// bf16 hi/lo split operands for tensor-core QKV
__device__ __nv_bfloat16 g_ahi[16384 * 768];
__device__ __nv_bfloat16 g_alo[16384 * 768];
__device__ __nv_bfloat16 g_whi[2304 * 768];
__device__ __nv_bfloat16 g_wlo[2304 * 768];

// ---------------- helpers ----------------
static __device__ __forceinline__ unsigned long long pk2(float lo, float hi) {
    unsigned long long r;
    asm("mov.b64 %0, {%1, %2};" : "=l"(r) : "f"(lo), "f"(hi));
    return r;
}
static __device__ __forceinline__ float2 upk2(unsigned long long v) {
    float2 r;
    asm("mov.b64 {%0, %1}, %2;" : "=f"(r.x), "=f"(r.y) : "l"(v));
    return r;
}
static __device__ __forceinline__ void ffma2(unsigned long long& d,
                                             unsigned long long a,
                                             unsigned long long b) {
    asm("fma.rn.f32x2 %0, %1, %2, %0;" : "+l"(d) : "l"(a), "l"(b));
}
static __device__ __forceinline__ void atomicMaxF(float* addr, float v) {
    if (v >= 0.f) atomicMax((int*)addr, __float_as_int(v));
    else          atomicMin((unsigned int*)addr, __float_as_uint(v));
}
static __device__ __forceinline__ unsigned smem_u32(const void* p) {
    unsigned a;
    asm("{ .reg .u64 t; cvta.to.shared.u64 t, %1; cvt.u32.u64 %0, t; }" : "=r"(a) : "l"(p));
    return a;
}

static __device__ __forceinline__ void ldmx4(unsigned& r0, unsigned& r1,
                                             unsigned& r2, unsigned& r3, unsigned a) {
    asm volatile("ldmatrix.sync.aligned.m8n8.x4.shared.b16 {%0,%1,%2,%3}, [%4];"
                 : "=r"(r0), "=r"(r1), "=r"(r2), "=r"(r3) : "r"(a));
}
static __device__ __forceinline__ void ldmx2(unsigned& r0, unsigned& r1, unsigned a) {
    asm volatile("ldmatrix.sync.aligned.m8n8.x2.shared.b16 {%0,%1}, [%2];"
                 : "=r"(r0), "=r"(r1) : "r"(a));
}
static __device__ __forceinline__ void mma16816(float* c, const unsigned* a,
                                                const unsigned* b) {
    asm volatile(
        "mma.sync.aligned.m16n8k16.row.col.f32.bf16.bf16.f32 "
        "{%0,%1,%2,%3}, {%4,%5,%6,%7}, {%8,%9}, {%0,%1,%2,%3};"
        : "+f"(c[0]), "+f"(c[1]), "+f"(c[2]), "+f"(c[3])
        : "r"(a[0]), "r"(a[1]), "r"(a[2]), "r"(a[3]), "r"(b[0]), "r"(b[1]));
}

#define CP16(dst, src) \
    asm volatile("cp.async.ca.shared.global [%0], [%1], 16;" :: "r"(dst), "l"(src))
#define CP_COMMIT() asm volatile("cp.async.commit_group;" ::: "memory")
#define CP_WAIT1()  asm volatile("cp.async.wait_group 1;" ::: "memory")
#define CP_WAIT0()  asm volatile("cp.async.wait_group 0;" ::: "memory")

__global__ void perf_init_kernel() {
    if (threadIdx.x < BH_) g_kmax[threadIdx.x] = -INFINITY;
}

// ---------------- hi/lo bf16 split of activations & weights ----------------
__global__ __launch_bounds__(256)
void perf_cvt_a(const float* __restrict__ hs) {
    int i = blockIdx.x * blockDim.x + threadIdx.x;      // float4 index
    const int T4 = 16384 * 768 / 4;
    if (i >= T4) return;
    float4 v = ((const float4*)hs)[i];
    __nv_bfloat16 hx = __float2bfloat16_rn(v.x), hy = __float2bfloat16_rn(v.y);
    __nv_bfloat16 hz = __float2bfloat16_rn(v.z), hw = __float2bfloat16_rn(v.w);
    __nv_bfloat162* ph = (__nv_bfloat162*)(g_ahi + i * 4);
    ph[0] = __nv_bfloat162(hx, hy);
    ph[1] = __nv_bfloat162(hz, hw);
    __nv_bfloat162* pl = (__nv_bfloat162*)(g_alo + i * 4);
    pl[0] = __nv_bfloat162(__float2bfloat16_rn(v.x - __bfloat162float(hx)),
                           __float2bfloat16_rn(v.y - __bfloat162float(hy)));
    pl[1] = __nv_bfloat162(__float2bfloat16_rn(v.z - __bfloat162float(hz)),
                           __float2bfloat16_rn(v.w - __bfloat162float(hw)));
}

__global__ __launch_bounds__(256)
void perf_cvt_w(const float* __restrict__ Wq, const float* __restrict__ Wk,
                const float* __restrict__ Wv) {
    int i = blockIdx.x * blockDim.x + threadIdx.x;      // float4 index
    const int T4 = 2304 * 768 / 4;
    if (i >= T4) return;
    int e = i * 4;
    int row = e / 768, col = e - row * 768;
    int z = row / 768;
    const float* W = (z == 0) ? Wq : (z == 1) ? Wk : Wv;
    float4 v = *(const float4*)(W + (size_t)(row - z * 768) * 768 + col);
    __nv_bfloat16 hx = __float2bfloat16_rn(v.x), hy = __float2bfloat16_rn(v.y);
    __nv_bfloat16 hz = __float2bfloat16_rn(v.z), hw = __float2bfloat16_rn(v.w);
    __nv_bfloat162* ph = (__nv_bfloat162*)(g_whi + e);
    ph[0] = __nv_bfloat162(hx, hy);
    ph[1] = __nv_bfloat162(hz, hw);
    __nv_bfloat162* pl = (__nv_bfloat162*)(g_wlo + e);
    pl[0] = __nv_bfloat162(__float2bfloat16_rn(v.x - __bfloat162float(hx)),
                           __float2bfloat16_rn(v.y - __bfloat162float(hy)));
    pl[1] = __nv_bfloat162(__float2bfloat16_rn(v.z - __bfloat162float(hz)),
                           __float2bfloat16_rn(v.w - __bfloat162float(hw)));
}

// ---------------- QKV GEMM on HMMA: block 128x128, 4 warps 64x64, cp.async x2 --
#define QROW 80
#define S_AH 0
#define S_AL (128 * QROW)
#define S_BH (2 * 128 * QROW)
#define S_BL (3 * 128 * QROW)
#define SSTAGE (4 * 128 * QROW)              // 40960 bytes
#define QKV_SMEM (2 * SSTAGE + 128 * 4)

__global__ __launch_bounds__(128, 2)
void perf_qkv_mma(const float* __restrict__ bq, const float* __restrict__ bk,
                  const float* __restrict__ bv) {
    extern __shared__ __align__(16) unsigned char smq[];
    float* bias_s = (float*)(smq + 2 * SSTAGE);
    unsigned sb = smem_u32(smq);

    int tid = threadIdx.x, wid = tid >> 5, lane = tid & 31;
    int warp_m = wid & 1, warp_n = wid >> 1;          // 2 x 2 grid of 64x64 tiles
    int m0 = blockIdx.x * 128;
    int n0 = blockIdx.y * 128;                        // row in concatenated W [2304]
    int z = blockIdx.y / 6;                           // 0=q, 1=k, 2=v
    int o_base = (blockIdx.y - z * 6) * 128;
    const float* bias = (z == 0) ? bq : (z == 1) ? bk : bv;
    float* dst = (z == 0) ? g_q : (z == 1) ? g_k : g_v;
    bias_s[tid] = bias[o_base + tid];

    float acc[4][8][4];
#pragma unroll
    for (int mt = 0; mt < 4; mt++)
#pragma unroll
        for (int nt = 0; nt < 8; nt++)
#pragma unroll
            for (int e = 0; e < 4; e++) acc[mt][nt][e] = 0.f;

    // per-thread cp.async assignments: 4 (r,seg) pairs for A rows, 4 for B rows
    int rA = tid >> 2, segA = tid & 3;                // base pattern; add i*32 rows

    // prefetch chunk 0
    {
        int k0 = 0;
        unsigned st = sb;
#pragma unroll
        for (int i = 0; i < 4; i++) {
            int r = rA + i * 32;
            size_t go = (size_t)(m0 + r) * 768 + k0 + segA * 8;
            unsigned so = (unsigned)(r * QROW + segA * 16);
            CP16(st + S_AH + so, g_ahi + go);
            CP16(st + S_AL + so, g_alo + go);
            size_t gb = (size_t)(n0 + r) * 768 + k0 + segA * 8;
            CP16(st + S_BH + so, g_whi + gb);
            CP16(st + S_BL + so, g_wlo + gb);
        }
        CP_COMMIT();
    }

    for (int ch = 0; ch < 24; ch++) {
        unsigned st = sb + (unsigned)((ch & 1) * SSTAGE);
        if (ch < 23) {
            int k0 = (ch + 1) * 32;
            unsigned st2 = sb + (unsigned)(((ch + 1) & 1) * SSTAGE);
#pragma unroll
            for (int i = 0; i < 4; i++) {
                int r = rA + i * 32;
                size_t go = (size_t)(m0 + r) * 768 + k0 + segA * 8;
                unsigned so = (unsigned)(r * QROW + segA * 16);
                CP16(st2 + S_AH + so, g_ahi + go);
                CP16(st2 + S_AL + so, g_alo + go);
                size_t gb = (size_t)(n0 + r) * 768 + k0 + segA * 8;
                CP16(st2 + S_BH + so, g_whi + gb);
                CP16(st2 + S_BL + so, g_wlo + gb);
            }
            CP_COMMIT();
            CP_WAIT1();
        } else {
            CP_WAIT0();
        }
        __syncthreads();

#pragma unroll
        for (int ks = 0; ks < 2; ks++) {
            unsigned ah[4][4], al[4][4];
#pragma unroll
            for (int mt = 0; mt < 4; mt++) {
                unsigned ra = (unsigned)((warp_m * 64 + mt * 16 + (lane & 15)) * QROW +
                                         ks * 32 + (lane >> 4) * 16);
                ldmx4(ah[mt][0], ah[mt][1], ah[mt][2], ah[mt][3], st + S_AH + ra);
                ldmx4(al[mt][0], al[mt][1], al[mt][2], al[mt][3], st + S_AL + ra);
            }
#pragma unroll
            for (int nt = 0; nt < 8; nt++) {
                unsigned rb = (unsigned)((warp_n * 64 + nt * 8 + (lane & 7)) * QROW +
                                         ks * 32 + ((lane >> 3) & 1) * 16);
                unsigned bh[2], bl[2];
                ldmx2(bh[0], bh[1], st + S_BH + rb);
                ldmx2(bl[0], bl[1], st + S_BL + rb);
#pragma unroll
                for (int mt = 0; mt < 4; mt++) {
                    mma16816(acc[mt][nt], ah[mt], bh);
                    mma16816(acc[mt][nt], ah[mt], bl);
                    mma16816(acc[mt][nt], al[mt], bh);
                }
            }
        }
        __syncthreads();
    }

    // epilogue: add bias, store to [b,h,n,d]
#pragma unroll
    for (int mt = 0; mt < 4; mt++) {
#pragma unroll
        for (int nt = 0; nt < 8; nt++) {
            int cb = warp_n * 64 + nt * 8 + (lane & 3) * 2;   // col within block
            int oc = o_base + cb;
            int h = oc >> 6, d = oc & 63;
            float bx = bias_s[cb], by = bias_s[cb + 1];
#pragma unroll
            for (int hh = 0; hh < 2; hh++) {
                int gi = m0 + warp_m * 64 + mt * 16 + (lane >> 2) + hh * 8;
                int bbi = gi >> 12, nn = gi & (N_ - 1);
                float2 v = make_float2(acc[mt][nt][hh * 2 + 0] + bx,
                                       acc[mt][nt][hh * 2 + 1] + by);
                *(float2*)(dst + ((size_t)(bbi * H_ + h) * N_ + nn) * DH_ + d) = v;
            }
        }
    }
}

// ---------------- FAVOR+ feature map (12-row x 3-tgroup blocked, f32x2) --------
#define FEAT_PS   (288 * 68)
#define FEAT_QS   (24 * 64)
#define FEAT_SMEM ((FEAT_PS + FEAT_QS + 24 + 24) * 4)

__global__ __launch_bounds__(192)
void perf_feat_kernel(const float* __restrict__ proj) {
    extern __shared__ float sm[];
    float* ps = sm;
    float* qs = sm + FEAT_PS;
    float* diag_s = sm + FEAT_PS + FEAT_QS;
    float* rowmax_s = diag_s + 24;

    int tid = threadIdx.x;
    int which = blockIdx.y;
    const float* src = which ? g_k : g_q;
    float* dstp      = which ? g_kp : g_qp;

    if (tid < 24) rowmax_s[tid] = -INFINITY;

    for (int i = tid; i < 288 * 17; i += 192) {
        int row = i / 17, c4 = i - row * 17;
        float4 v = make_float4(0.f, 0.f, 0.f, 0.f);
        if (row < NB_ && c4 < 16) v = *(const float4*)(proj + row * 64 + c4 * 4);
        *(float4*)(&ps[row * 68 + c4 * 4]) = v;
    }
    int rbase24 = blockIdx.x * 24;
    for (int i = tid; i < 24 * 16; i += 192) {
        int row = i >> 4, c4 = i & 15;
        *(float4*)(&qs[row * 64 + c4 * 4]) =
            *(const float4*)(src + (size_t)(rbase24 + row) * 64 + c4 * 4);
    }
    __syncthreads();

    if (tid < 24) {
        float s = 0.f;
#pragma unroll
        for (int c = 0; c < 16; c++) {
            float4 v = *(float4*)(&qs[tid * 64 + c * 4]);
            s += v.x * v.x + v.y * v.y + v.z * v.z + v.w * v.w;
        }
        diag_s[tid] = 0.0625f * s;
        if (which) g_kdiag[rbase24 + tid] = 0.0625f * s;
    }

    int w = tid >> 5, lane = tid & 31;
    int rg = (w >= 3) ? 1 : 0;
    int g = w - rg * 3;
    int rbase = rg * 12;

    unsigned long long acc2[12][3];
#pragma unroll
    for (int r = 0; r < 12; r++)
#pragma unroll
        for (int t = 0; t < 3; t++) acc2[r][t] = 0ull;

#pragma unroll 4
    for (int d4 = 0; d4 < 16; d4++) {
        unsigned long long pp[3][2];
#pragma unroll
        for (int t = 0; t < 3; t++) {
            float4 p = *(float4*)(&ps[(lane + (g * 3 + t) * 32) * 68 + d4 * 4]);
            pp[t][0] = pk2(p.x, p.y);
            pp[t][1] = pk2(p.z, p.w);
        }
#pragma unroll
        for (int r = 0; r < 12; r++) {
            float4 q = *(float4*)(&qs[(rbase + r) * 64 + d4 * 4]);
            unsigned long long qa = pk2(q.x, q.y), qb = pk2(q.z, q.w);
#pragma unroll
            for (int t = 0; t < 3; t++) {
                ffma2(acc2[r][t], qa, pp[t][0]);
                ffma2(acc2[r][t], qb, pp[t][1]);
            }
        }
    }

    const float DN = 0.3535533905932738f;
    const float RATIO = 0.06131393394849658f;

    if (which == 0) {
#pragma unroll
        for (int r = 0; r < 12; r++) {
            float m = -INFINITY;
#pragma unroll
            for (int t = 0; t < 3; t++) {
                int j = lane + (g * 3 + t) * 32;
                float2 u = upk2(acc2[r][t]);
                float v = u.x + u.y;
                if (j < NB_) m = fmaxf(m, v);
            }
#pragma unroll
            for (int o = 16; o; o >>= 1) m = fmaxf(m, __shfl_xor_sync(0xffffffffu, m, o));
            if (lane == 0) atomicMaxF(&rowmax_s[rbase + r], m * DN);
        }
        __syncthreads();
#pragma unroll
        for (int r = 0; r < 12; r++) {
            int rl = rbase + r;
            float c = diag_s[rl] + rowmax_s[rl];
            float* dr = dstp + (size_t)(rbase24 + rl) * NB_;
#pragma unroll
            for (int t = 0; t < 3; t++) {
                int j = lane + (g * 3 + t) * 32;
                if (j < NB_) {
                    float2 u = upk2(acc2[r][t]);
                    dr[j] = RATIO * (expf((u.x + u.y) * DN - c) + EPS_);
                }
            }
        }
    } else {
        float curmax = -INFINITY;
        int curbh = (rbase24 + rbase) >> 12;
#pragma unroll
        for (int r = 0; r < 12; r++) {
            int row = rbase24 + rbase + r;
            float* dr = dstp + (size_t)row * NB_;
            float m = -INFINITY;
#pragma unroll
            for (int t = 0; t < 3; t++) {
                int j = lane + (g * 3 + t) * 32;
                float2 u = upk2(acc2[r][t]);
                float v = u.x + u.y;
                if (j < NB_) { dr[j] = v * DN; m = fmaxf(m, v); }
            }
#pragma unroll
            for (int o = 16; o; o >>= 1) m = fmaxf(m, __shfl_xor_sync(0xffffffffu, m, o));
            if (lane == 0) {
                int bh = row >> 12;
                if (bh != curbh) {
                    atomicMaxF(&g_kmax[curbh], curmax);
                    curmax = -INFINITY;
                    curbh = bh;
                }
                curmax = fmaxf(curmax, m * DN);
            }
        }
        if (lane == 0) atomicMaxF(&g_kmax[curbh], curmax);
    }
}

// ---------------- k_sum (fused exp transform; deterministic two-stage) --------
__global__ void perf_ksumA_kernel() {
    const float RATIO = 0.06131393394849658f;
    int bh = blockIdx.y, ch = blockIdx.x, j = threadIdx.x;
    if (j >= NB_) return;
    float kmaxv = g_kmax[bh];
    const float* base = g_kp + ((size_t)(bh * N_ + ch * 128)) * NB_ + j;
    const float* dg = g_kdiag + bh * N_ + ch * 128;
    float s = 0.f;
#pragma unroll 4
    for (int r = 0; r < 128; r++)
        s += RATIO * (expf(base[(size_t)r * NB_] - dg[r] - kmaxv) + EPS_);
    g_ksum_part[(bh * 32 + ch) * NB_ + j] = s;
}

__global__ void perf_ksumB_kernel() {
    int bh = blockIdx.x, j = threadIdx.x;
    if (j >= NB_) return;
    float s = 0.f;
#pragma unroll
    for (int c = 0; c < 32; c++) s += g_ksum_part[(bh * 32 + c) * NB_ + j];
    g_ksum[bh * NB_ + j] = s;
}

// ---------------- ctx = kp^T v (exp transform fused into tile load) -----------
__global__ __launch_bounds__(256)
void perf_ctx_kernel() {
    const float RATIO = 0.06131393394849658f;
    __shared__ float kt[16][68];
    __shared__ float vt[16][68];
    int jt = blockIdx.x, ks = blockIdx.y, bh = blockIdx.z;
    int j0 = jt * 64, n0 = ks * 1024;
    int tid = threadIdx.x, tx = tid & 15, ty = tid >> 4;
    const float* kbase = g_kp + (size_t)bh * N_ * NB_;
    const float* vbase = g_v + (size_t)bh * N_ * DH_;
    const float* dgbase = g_kdiag + bh * N_;
    float kmaxv = g_kmax[bh];

    unsigned long long acc2[4][2];
#pragma unroll
    for (int a = 0; a < 4; a++) { acc2[a][0] = 0ull; acc2[a][1] = 0ull; }

    for (int nn = 0; nn < 1024; nn += 16) {
#pragma unroll
        for (int i = 0; i < 2; i++) {
            int id = i * 256 + tid;
            int r = id >> 5, c2 = id & 31;
            int j = j0 + c2 * 2;
            float2 o = make_float2(0.f, 0.f);
            if (j + 1 < NB_) {
                int row = n0 + nn + r;
                float c = dgbase[row] + kmaxv;
                float2 v = *(const float2*)(kbase + (size_t)row * NB_ + j);
                o.x = RATIO * (expf(v.x - c) + EPS_);
                o.y = RATIO * (expf(v.y - c) + EPS_);
            }
            kt[r][c2 * 2] = o.x;
            kt[r][c2 * 2 + 1] = o.y;
        }
        {
            int r = tid >> 4, c4 = tid & 15;
            float4 v = *(const float4*)(vbase + (size_t)(n0 + nn + r) * DH_ + c4 * 4);
            *(float4*)(&vt[r][c4 * 4]) = v;
        }
        __syncthreads();
#pragma unroll
        for (int k = 0; k < 16; k++) {
            float4 a = *(float4*)(&kt[k][ty * 4]);
            float4 b = *(float4*)(&vt[k][tx * 4]);
            unsigned long long b01 = pk2(b.x, b.y);
            unsigned long long b23 = pk2(b.z, b.w);
            float av[4] = {a.x, a.y, a.z, a.w};
#pragma unroll
            for (int i = 0; i < 4; i++) {
                unsigned long long ad = pk2(av[i], av[i]);
                ffma2(acc2[i][0], ad, b01);
                ffma2(acc2[i][1], ad, b23);
            }
        }
        __syncthreads();
    }

    float* obase = g_ctx_part + (size_t)(ks * BH_ + bh) * NB_ * DH_;
#pragma unroll
    for (int jj = 0; jj < 4; jj++) {
        int j = j0 + ty * 4 + jj;
        if (j < NB_) {
            float2 p0 = upk2(acc2[jj][0]);
            float2 p1 = upk2(acc2[jj][1]);
            *(float4*)(&obase[(size_t)j * DH_ + tx * 4]) =
                make_float4(p0.x, p0.y, p1.x, p1.y);
        }
    }
}

__global__ void perf_ctxred_kernel() {
    const int T = BH_ * NB_ * DH_;
    int i = blockIdx.x * blockDim.x + threadIdx.x;
    if (i >= T) return;
    g_ctx[i] = g_ctx_part[i] + g_ctx_part[i + T] + g_ctx_part[i + 2 * T] + g_ctx_part[i + 3 * T];
}

// ---------------- out = (qp @ ctx) / (qp @ ksum) ----------------
#define OUT_QS_W (8 * 272)
#define OUT_SMEM ((NB_ * DH_ + 268 + 16 * OUT_QS_W) * 4)

__global__ __launch_bounds__(512)
void perf_out_kernel(float* __restrict__ out) {
    extern __shared__ float sm[];
    float* ctx_s = sm;
    float* ksum_s = sm + NB_ * DH_;
    float* qsall = sm + NB_ * DH_ + 268;
    int tid = threadIdx.x, w = tid >> 5, lane = tid & 31;
    int row0 = blockIdx.x * 256;
    int bh = row0 >> 12;

    const float* cb = g_ctx + (size_t)bh * NB_ * DH_;
    for (int i = tid; i < NB_ * DH_ / 4; i += 512)
        *(float4*)(&ctx_s[i * 4]) = *(const float4*)(cb + i * 4);
    for (int i = tid; i < NB_; i += 512) ksum_s[i] = g_ksum[bh * NB_ + i];
    __syncthreads();

    int bb = bh / H_, h = bh - bb * H_;
    float* qs = qsall + w * OUT_QS_W;

    for (int grp = 0; grp < 2; grp++) {
        int rowg = row0 + w * 16 + grp * 8;

        __syncwarp();
#pragma unroll
        for (int r = 0; r < 8; r++) {
            const float2* qr = (const float2*)(g_qp + (size_t)(rowg + r) * NB_);
#pragma unroll
            for (int k = 0; k < 5; k++) {
                int idx = lane + 32 * k;
                if (idx < NB_ / 2) {
                    float2 v = qr[idx];
                    qs[r * 272 + idx * 2] = v.x;
                    qs[r * 272 + idx * 2 + 1] = v.y;
                }
            }
        }
        __syncwarp();

        float dinv[8];
#pragma unroll
        for (int r = 0; r < 8; r++) {
            float s = 0.f;
#pragma unroll
            for (int t = 0; t < 9; t++) {
                int j = lane + 32 * t;
                if (j < NB_) s += qs[r * 272 + j] * ksum_s[j];
            }
#pragma unroll
            for (int o = 16; o; o >>= 1) s += __shfl_xor_sync(0xffffffffu, s, o);
            dinv[r] = 1.0f / s;
        }

        unsigned long long acc2[8];
#pragma unroll
        for (int r = 0; r < 8; r++) acc2[r] = 0ull;

        for (int j0 = 0; j0 < 264; j0 += 4) {
            float qv[8][4];
#pragma unroll
            for (int r = 0; r < 8; r++)
                *(float4*)qv[r] = *(float4*)(&qs[r * 272 + j0]);
#pragma unroll
            for (int jj = 0; jj < 4; jj++) {
                unsigned long long c = *(const unsigned long long*)(&ctx_s[(j0 + jj) * 64 + 2 * lane]);
#pragma unroll
                for (int r = 0; r < 8; r++) {
                    unsigned long long ad = pk2(qv[r][jj], qv[r][jj]);
                    ffma2(acc2[r], ad, c);
                }
            }
        }
#pragma unroll
        for (int jj = 264; jj < NB_; jj++) {
            unsigned long long c = *(const unsigned long long*)(&ctx_s[jj * 64 + 2 * lane]);
#pragma unroll
            for (int r = 0; r < 8; r++) {
                float qv = qs[r * 272 + jj];
                unsigned long long ad = pk2(qv, qv);
                ffma2(acc2[r], ad, c);
            }
        }

#pragma unroll
        for (int r = 0; r < 8; r++) {
            int row = rowg + r;
            int n = row & (N_ - 1);
            float2 u = upk2(acc2[r]);
            *(float2*)(out + ((size_t)(bb * N_ + n)) * 768 + h * 64 + 2 * lane) =
                make_float2(u.x * dinv[r], u.y * dinv[r]);
        }
    }
}

// ---------------- launch ----------------
extern "C" void kernel_launch(void* const* d_in, const int* in_sizes, int n_in,
                              void* d_out, int out_size) {
    (void)in_sizes; (void)n_in; (void)out_size;
    const float* hs   = (const float*)d_in[0];
    const float* Wq   = (const float*)d_in[1];
    const float* bq   = (const float*)d_in[2];
    const float* Wk   = (const float*)d_in[3];
    const float* bk   = (const float*)d_in[4];
    const float* Wv   = (const float*)d_in[5];
    const float* bv   = (const float*)d_in[6];
    const float* proj = (const float*)d_in[7];
    float* out = (float*)d_out;

    cudaFuncSetAttribute(perf_qkv_mma,     cudaFuncAttributeMaxDynamicSharedMemorySize, QKV_SMEM);
    cudaFuncSetAttribute(perf_feat_kernel, cudaFuncAttributeMaxDynamicSharedMemorySize, FEAT_SMEM);
    cudaFuncSetAttribute(perf_out_kernel,  cudaFuncAttributeMaxDynamicSharedMemorySize, OUT_SMEM);

    perf_init_kernel<<<1, 64>>>();
    perf_cvt_a<<<(16384 * 768 / 4 + 255) / 256, 256>>>(hs);
    perf_cvt_w<<<(2304 * 768 / 4 + 255) / 256, 256>>>(Wq, Wk, Wv);
    perf_qkv_mma<<<dim3(128, 18), 128, QKV_SMEM>>>(bq, bk, bv);
    perf_feat_kernel<<<dim3(R_ / 24, 2), 192, FEAT_SMEM>>>(proj);
    perf_ksumA_kernel<<<dim3(32, BH_), 288>>>();
    perf_ksumB_kernel<<<BH_, 288>>>();
    perf_ctx_kernel<<<dim3(5, 4, BH_), 256>>>();
    perf_ctxred_kernel<<<(BH_ * NB_ * DH_ + 255) / 256, 256>>>();
    perf_out_kernel<<<R_ / 256, 512, OUT_SMEM>>>(out);
}

// round 15
// speedup vs baseline: 2.7531x; 1.2685x over previous
#include <cuda_runtime.h>
#include <cuda_bf16.h>
#include <math.h>

#define B_   4
#define N_   4096
#define H_   12
#define DH_  64
#define NB_  266
#define BH_  (B_*H_)           // 48
#define R_   (B_*H_*N_)        // 196608
#define EPS_ 1e-4f

// ---------------- scratch (static device memory; no allocation) ----------------
__device__ float g_v[R_ * DH_];
__device__ float g_qp[R_ * NB_];
__device__ float g_kp[R_ * NB_];           // raw dash (never transformed in place)
__device__ float g_kdiag[R_];
__device__ float g_kmax[BH_];
__device__ float g_ksum_part[BH_ * 32 * NB_];
__device__ float g_ksum[BH_ * NB_];
__device__ float g_ctx_part[4 * BH_ * NB_ * DH_];
__device__ float g_ctx[BH_ * NB_ * DH_];
// bf16 hi/lo split operands
__device__ __nv_bfloat16 g_ahi[16384 * 768];
__device__ __nv_bfloat16 g_alo[16384 * 768];
__device__ __nv_bfloat16 g_whi[2304 * 768];
__device__ __nv_bfloat16 g_wlo[2304 * 768];
__device__ __nv_bfloat16 g_qhi[R_ * DH_];
__device__ __nv_bfloat16 g_qlo[R_ * DH_];
__device__ __nv_bfloat16 g_khi[R_ * DH_];
__device__ __nv_bfloat16 g_klo[R_ * DH_];
__device__ __nv_bfloat16 g_phi[288 * DH_];
__device__ __nv_bfloat16 g_plo[288 * DH_];

// ---------------- helpers ----------------
static __device__ __forceinline__ unsigned long long pk2(float lo, float hi) {
    unsigned long long r;
    asm("mov.b64 %0, {%1, %2};" : "=l"(r) : "f"(lo), "f"(hi));
    return r;
}
static __device__ __forceinline__ float2 upk2(unsigned long long v) {
    float2 r;
    asm("mov.b64 {%0, %1}, %2;" : "=f"(r.x), "=f"(r.y) : "l"(v));
    return r;
}
static __device__ __forceinline__ void ffma2(unsigned long long& d,
                                             unsigned long long a,
                                             unsigned long long b) {
    asm("fma.rn.f32x2 %0, %1, %2, %0;" : "+l"(d) : "l"(a), "l"(b));
}
static __device__ __forceinline__ void atomicMaxF(float* addr, float v) {
    if (v >= 0.f) atomicMax((int*)addr, __float_as_int(v));
    else          atomicMin((unsigned int*)addr, __float_as_uint(v));
}
static __device__ __forceinline__ unsigned smem_u32(const void* p) {
    unsigned a;
    asm("{ .reg .u64 t; cvta.to.shared.u64 t, %1; cvt.u32.u64 %0, t; }" : "=r"(a) : "l"(p));
    return a;
}

static __device__ __forceinline__ void ldmx4(unsigned& r0, unsigned& r1,
                                             unsigned& r2, unsigned& r3, unsigned a) {
    asm volatile("ldmatrix.sync.aligned.m8n8.x4.shared.b16 {%0,%1,%2,%3}, [%4];"
                 : "=r"(r0), "=r"(r1), "=r"(r2), "=r"(r3) : "r"(a));
}
static __device__ __forceinline__ void ldmx2(unsigned& r0, unsigned& r1, unsigned a) {
    asm volatile("ldmatrix.sync.aligned.m8n8.x2.shared.b16 {%0,%1}, [%2];"
                 : "=r"(r0), "=r"(r1) : "r"(a));
}
static __device__ __forceinline__ void mma16816(float* c, const unsigned* a,
                                                const unsigned* b) {
    asm volatile(
        "mma.sync.aligned.m16n8k16.row.col.f32.bf16.bf16.f32 "
        "{%0,%1,%2,%3}, {%4,%5,%6,%7}, {%8,%9}, {%0,%1,%2,%3};"
        : "+f"(c[0]), "+f"(c[1]), "+f"(c[2]), "+f"(c[3])
        : "r"(a[0]), "r"(a[1]), "r"(a[2]), "r"(a[3]), "r"(b[0]), "r"(b[1]));
}

#define CP16(dst, src) \
    asm volatile("cp.async.ca.shared.global [%0], [%1], 16;" :: "r"(dst), "l"(src))
#define CP_COMMIT() asm volatile("cp.async.commit_group;" ::: "memory")
#define CP_WAIT1()  asm volatile("cp.async.wait_group 1;" ::: "memory")
#define CP_WAIT0()  asm volatile("cp.async.wait_group 0;" ::: "memory")

__global__ void perf_init_kernel() {
    if (threadIdx.x < BH_) g_kmax[threadIdx.x] = -INFINITY;
}

// ---------------- hi/lo bf16 splits ----------------
__global__ __launch_bounds__(256)
void perf_cvt_a(const float* __restrict__ hs) {
    int i = blockIdx.x * blockDim.x + threadIdx.x;      // float4 index
    const int T4 = 16384 * 768 / 4;
    if (i >= T4) return;
    float4 v = ((const float4*)hs)[i];
    __nv_bfloat16 hx = __float2bfloat16_rn(v.x), hy = __float2bfloat16_rn(v.y);
    __nv_bfloat16 hz = __float2bfloat16_rn(v.z), hw = __float2bfloat16_rn(v.w);
    __nv_bfloat162* ph = (__nv_bfloat162*)(g_ahi + i * 4);
    ph[0] = __nv_bfloat162(hx, hy);
    ph[1] = __nv_bfloat162(hz, hw);
    __nv_bfloat162* pl = (__nv_bfloat162*)(g_alo + i * 4);
    pl[0] = __nv_bfloat162(__float2bfloat16_rn(v.x - __bfloat162float(hx)),
                           __float2bfloat16_rn(v.y - __bfloat162float(hy)));
    pl[1] = __nv_bfloat162(__float2bfloat16_rn(v.z - __bfloat162float(hz)),
                           __float2bfloat16_rn(v.w - __bfloat162float(hw)));
}

__global__ __launch_bounds__(256)
void perf_cvt_w(const float* __restrict__ Wq, const float* __restrict__ Wk,
                const float* __restrict__ Wv) {
    int i = blockIdx.x * blockDim.x + threadIdx.x;      // float4 index
    const int T4 = 2304 * 768 / 4;
    if (i >= T4) return;
    int e = i * 4;
    int row = e / 768, col = e - row * 768;
    int z = row / 768;
    const float* W = (z == 0) ? Wq : (z == 1) ? Wk : Wv;
    float4 v = *(const float4*)(W + (size_t)(row - z * 768) * 768 + col);
    __nv_bfloat16 hx = __float2bfloat16_rn(v.x), hy = __float2bfloat16_rn(v.y);
    __nv_bfloat16 hz = __float2bfloat16_rn(v.z), hw = __float2bfloat16_rn(v.w);
    __nv_bfloat162* ph = (__nv_bfloat162*)(g_whi + e);
    ph[0] = __nv_bfloat162(hx, hy);
    ph[1] = __nv_bfloat162(hz, hw);
    __nv_bfloat162* pl = (__nv_bfloat162*)(g_wlo + e);
    pl[0] = __nv_bfloat162(__float2bfloat16_rn(v.x - __bfloat162float(hx)),
                           __float2bfloat16_rn(v.y - __bfloat162float(hy)));
    pl[1] = __nv_bfloat162(__float2bfloat16_rn(v.z - __bfloat162float(hz)),
                           __float2bfloat16_rn(v.w - __bfloat162float(hw)));
}

__global__ __launch_bounds__(256)
void perf_cvt_p(const float* __restrict__ proj) {
    int i = blockIdx.x * blockDim.x + threadIdx.x;      // float4 index
    const int T4 = 288 * 64 / 4;
    if (i >= T4) return;
    int e = i * 4;
    int row = e >> 6;
    float4 v = make_float4(0.f, 0.f, 0.f, 0.f);
    if (row < NB_) v = *(const float4*)(proj + e);
    __nv_bfloat16 hx = __float2bfloat16_rn(v.x), hy = __float2bfloat16_rn(v.y);
    __nv_bfloat16 hz = __float2bfloat16_rn(v.z), hw = __float2bfloat16_rn(v.w);
    __nv_bfloat162* ph = (__nv_bfloat162*)(g_phi + e);
    ph[0] = __nv_bfloat162(hx, hy);
    ph[1] = __nv_bfloat162(hz, hw);
    __nv_bfloat162* pl = (__nv_bfloat162*)(g_plo + e);
    pl[0] = __nv_bfloat162(__float2bfloat16_rn(v.x - __bfloat162float(hx)),
                           __float2bfloat16_rn(v.y - __bfloat162float(hy)));
    pl[1] = __nv_bfloat162(__float2bfloat16_rn(v.z - __bfloat162float(hz)),
                           __float2bfloat16_rn(v.w - __bfloat162float(hw)));
}

// ---------------- QKV GEMM on HMMA: block 128x128, 4 warps 64x64, cp.async x2 --
#define QROW 80
#define S_AH 0
#define S_AL (128 * QROW)
#define S_BH (2 * 128 * QROW)
#define S_BL (3 * 128 * QROW)
#define SSTAGE (4 * 128 * QROW)              // 40960 bytes
#define QKV_SMEM (2 * SSTAGE + 128 * 4)

__global__ __launch_bounds__(128, 2)
void perf_qkv_mma(const float* __restrict__ bq, const float* __restrict__ bk,
                  const float* __restrict__ bv) {
    extern __shared__ __align__(16) unsigned char smq[];
    float* bias_s = (float*)(smq + 2 * SSTAGE);
    unsigned sb = smem_u32(smq);

    int tid = threadIdx.x, wid = tid >> 5, lane = tid & 31;
    int warp_m = wid & 1, warp_n = wid >> 1;          // 2 x 2 grid of 64x64 tiles
    int m0 = blockIdx.x * 128;
    int n0 = blockIdx.y * 128;                        // row in concatenated W [2304]
    int z = blockIdx.y / 6;                           // 0=q, 1=k, 2=v
    int o_base = (blockIdx.y - z * 6) * 128;
    const float* bias = (z == 0) ? bq : (z == 1) ? bk : bv;
    bias_s[tid] = bias[o_base + tid];

    float acc[4][8][4];
#pragma unroll
    for (int mt = 0; mt < 4; mt++)
#pragma unroll
        for (int nt = 0; nt < 8; nt++)
#pragma unroll
            for (int e = 0; e < 4; e++) acc[mt][nt][e] = 0.f;

    int rA = tid >> 2, segA = tid & 3;

    {
        int k0 = 0;
        unsigned st = sb;
#pragma unroll
        for (int i = 0; i < 4; i++) {
            int r = rA + i * 32;
            size_t go = (size_t)(m0 + r) * 768 + k0 + segA * 8;
            unsigned so = (unsigned)(r * QROW + segA * 16);
            CP16(st + S_AH + so, g_ahi + go);
            CP16(st + S_AL + so, g_alo + go);
            size_t gb = (size_t)(n0 + r) * 768 + k0 + segA * 8;
            CP16(st + S_BH + so, g_whi + gb);
            CP16(st + S_BL + so, g_wlo + gb);
        }
        CP_COMMIT();
    }

    for (int ch = 0; ch < 24; ch++) {
        unsigned st = sb + (unsigned)((ch & 1) * SSTAGE);
        if (ch < 23) {
            int k0 = (ch + 1) * 32;
            unsigned st2 = sb + (unsigned)(((ch + 1) & 1) * SSTAGE);
#pragma unroll
            for (int i = 0; i < 4; i++) {
                int r = rA + i * 32;
                size_t go = (size_t)(m0 + r) * 768 + k0 + segA * 8;
                unsigned so = (unsigned)(r * QROW + segA * 16);
                CP16(st2 + S_AH + so, g_ahi + go);
                CP16(st2 + S_AL + so, g_alo + go);
                size_t gb = (size_t)(n0 + r) * 768 + k0 + segA * 8;
                CP16(st2 + S_BH + so, g_whi + gb);
                CP16(st2 + S_BL + so, g_wlo + gb);
            }
            CP_COMMIT();
            CP_WAIT1();
        } else {
            CP_WAIT0();
        }
        __syncthreads();

#pragma unroll
        for (int ks = 0; ks < 2; ks++) {
            unsigned ah[4][4], al[4][4];
#pragma unroll
            for (int mt = 0; mt < 4; mt++) {
                unsigned ra = (unsigned)((warp_m * 64 + mt * 16 + (lane & 15)) * QROW +
                                         ks * 32 + (lane >> 4) * 16);
                ldmx4(ah[mt][0], ah[mt][1], ah[mt][2], ah[mt][3], st + S_AH + ra);
                ldmx4(al[mt][0], al[mt][1], al[mt][2], al[mt][3], st + S_AL + ra);
            }
#pragma unroll
            for (int nt = 0; nt < 8; nt++) {
                unsigned rb = (unsigned)((warp_n * 64 + nt * 8 + (lane & 7)) * QROW +
                                         ks * 32 + ((lane >> 3) & 1) * 16);
                unsigned bh[2], bl[2];
                ldmx2(bh[0], bh[1], st + S_BH + rb);
                ldmx2(bl[0], bl[1], st + S_BL + rb);
#pragma unroll
                for (int mt = 0; mt < 4; mt++) {
                    mma16816(acc[mt][nt], ah[mt], bh);
                    mma16816(acc[mt][nt], ah[mt], bl);
                    mma16816(acc[mt][nt], al[mt], bh);
                }
            }
        }
        __syncthreads();
    }

    // epilogue: add bias; q/k stored as bf16 hi/lo, v as fp32
#pragma unroll
    for (int mt = 0; mt < 4; mt++) {
#pragma unroll
        for (int nt = 0; nt < 8; nt++) {
            int cb = warp_n * 64 + nt * 8 + (lane & 3) * 2;
            int oc = o_base + cb;
            int h = oc >> 6, d = oc & 63;
            float bx = bias_s[cb], by = bias_s[cb + 1];
#pragma unroll
            for (int hh = 0; hh < 2; hh++) {
                int gi = m0 + warp_m * 64 + mt * 16 + (lane >> 2) + hh * 8;
                int bbi = gi >> 12, nn = gi & (N_ - 1);
                size_t idx = ((size_t)(bbi * H_ + h) * N_ + nn) * DH_ + d;
                float vx = acc[mt][nt][hh * 2 + 0] + bx;
                float vy = acc[mt][nt][hh * 2 + 1] + by;
                if (z == 2) {
                    *(float2*)(g_v + idx) = make_float2(vx, vy);
                } else {
                    __nv_bfloat16* dh = z ? g_khi : g_qhi;
                    __nv_bfloat16* dl = z ? g_klo : g_qlo;
                    __nv_bfloat16 hx = __float2bfloat16_rn(vx);
                    __nv_bfloat16 hy = __float2bfloat16_rn(vy);
                    *(__nv_bfloat162*)(dh + idx) = __nv_bfloat162(hx, hy);
                    *(__nv_bfloat162*)(dl + idx) = __nv_bfloat162(
                        __float2bfloat16_rn(vx - __bfloat162float(hx)),
                        __float2bfloat16_rn(vy - __bfloat162float(hy)));
                }
            }
        }
    }
}

// ---------------- FAVOR+ feature map on HMMA --------------------------------
// Block: 128 rows x 288 cols (full NB padded). 8 warps (2m x 4n), warp 64x72.
// K = 64 (4 k16 steps), hi/lo 3-MMA split. Epilogue: rowmax/bhmax + exp fused.
#define FROW 144
#define FS_QH 0
#define FS_QL (128 * FROW)
#define FS_PH (2 * 128 * FROW)
#define FS_PL (FS_PH + 288 * FROW)
#define FS_DIAG (FS_PL + 288 * FROW)          // 119808
#define FS_RMAX (FS_DIAG + 512)
#define FEAT_SMEM (FS_RMAX + 512)

__global__ __launch_bounds__(256)
void perf_feat_mma() {
    extern __shared__ __align__(16) unsigned char smf[];
    float* diag_s = (float*)(smf + FS_DIAG);
    float* rmax_s = (float*)(smf + FS_RMAX);
    unsigned sb = smem_u32(smf);

    int tid = threadIdx.x, wid = tid >> 5, lane = tid & 31;
    int warp_m = wid & 1, warp_n = wid >> 1;
    int which = blockIdx.y;
    int row0 = blockIdx.x * 128;
    const __nv_bfloat16* srcH = which ? g_khi : g_qhi;
    const __nv_bfloat16* srcL = which ? g_klo : g_qlo;
    float* dstp = which ? g_kp : g_qp;

    if (tid < 128) rmax_s[tid] = -INFINITY;

    for (int i = tid; i < 128 * 8; i += 256) {
        int r = i >> 3, c = i & 7;
        *(uint4*)(smf + FS_QH + r * FROW + c * 16) =
            *(const uint4*)(srcH + (size_t)(row0 + r) * 64 + c * 8);
        *(uint4*)(smf + FS_QL + r * FROW + c * 16) =
            *(const uint4*)(srcL + (size_t)(row0 + r) * 64 + c * 8);
    }
    for (int i = tid; i < 288 * 8; i += 256) {
        int r = i >> 3, c = i & 7;
        *(uint4*)(smf + FS_PH + r * FROW + c * 16) = *(const uint4*)(g_phi + r * 64 + c * 8);
        *(uint4*)(smf + FS_PL + r * FROW + c * 16) = *(const uint4*)(g_plo + r * 64 + c * 8);
    }
    __syncthreads();

    // diag = 0.0625 * sum(x^2) (x = hi + lo)
    if (tid < 128) {
        const __nv_bfloat162* ph = (const __nv_bfloat162*)(smf + FS_QH + tid * FROW);
        const __nv_bfloat162* pl = (const __nv_bfloat162*)(smf + FS_QL + tid * FROW);
        float s = 0.f;
#pragma unroll
        for (int c = 0; c < 32; c++) {
            float2 h = __bfloat1622float2(ph[c]);
            float2 l = __bfloat1622float2(pl[c]);
            float x = h.x + l.x, y = h.y + l.y;
            s += x * x + y * y;
        }
        diag_s[tid] = 0.0625f * s;
        if (which) g_kdiag[row0 + tid] = 0.0625f * s;
    }

    float acc[4][9][4];
#pragma unroll
    for (int mt = 0; mt < 4; mt++)
#pragma unroll
        for (int nt = 0; nt < 9; nt++)
#pragma unroll
            for (int e = 0; e < 4; e++) acc[mt][nt][e] = 0.f;

#pragma unroll
    for (int ks = 0; ks < 4; ks++) {
        unsigned ah[4][4], al[4][4];
#pragma unroll
        for (int mt = 0; mt < 4; mt++) {
            unsigned ra = (unsigned)((warp_m * 64 + mt * 16 + (lane & 15)) * FROW +
                                     ks * 32 + (lane >> 4) * 16);
            ldmx4(ah[mt][0], ah[mt][1], ah[mt][2], ah[mt][3], sb + FS_QH + ra);
            ldmx4(al[mt][0], al[mt][1], al[mt][2], al[mt][3], sb + FS_QL + ra);
        }
#pragma unroll
        for (int nt = 0; nt < 9; nt++) {
            unsigned rb = (unsigned)((warp_n * 72 + nt * 8 + (lane & 7)) * FROW +
                                     ks * 32 + ((lane >> 3) & 1) * 16);
            unsigned bh[2], bl[2];
            ldmx2(bh[0], bh[1], sb + FS_PH + rb);
            ldmx2(bl[0], bl[1], sb + FS_PL + rb);
#pragma unroll
            for (int mt = 0; mt < 4; mt++) {
                mma16816(acc[mt][nt], ah[mt], bh);
                mma16816(acc[mt][nt], ah[mt], bl);
                mma16816(acc[mt][nt], al[mt], bh);
            }
        }
    }

    const float DN = 0.3535533905932738f;      // 64^-0.25
    const float RATIO = 0.06131393394849658f;  // 266^-0.5

    if (which == 0) {
        // per-row max: thread partial over its cols, quad shuffle, smem atomic
#pragma unroll
        for (int mt = 0; mt < 4; mt++) {
#pragma unroll
            for (int hh = 0; hh < 2; hh++) {
                float m = -INFINITY;
#pragma unroll
                for (int nt = 0; nt < 9; nt++) {
                    int col = warp_n * 72 + nt * 8 + (lane & 3) * 2;
                    if (col < NB_)
                        m = fmaxf(m, fmaxf(acc[mt][nt][hh * 2], acc[mt][nt][hh * 2 + 1]));
                }
                m = fmaxf(m, __shfl_xor_sync(0xffffffffu, m, 1));
                m = fmaxf(m, __shfl_xor_sync(0xffffffffu, m, 2));
                if ((lane & 3) == 0)
                    atomicMaxF(&rmax_s[warp_m * 64 + mt * 16 + (lane >> 2) + hh * 8], m * DN);
            }
        }
        __syncthreads();
#pragma unroll
        for (int mt = 0; mt < 4; mt++) {
#pragma unroll
            for (int hh = 0; hh < 2; hh++) {
                int rl = warp_m * 64 + mt * 16 + (lane >> 2) + hh * 8;
                float c = diag_s[rl] + rmax_s[rl];
                float* dr = dstp + (size_t)(row0 + rl) * NB_;
#pragma unroll
                for (int nt = 0; nt < 9; nt++) {
                    int col = warp_n * 72 + nt * 8 + (lane & 3) * 2;
                    if (col < NB_) {
                        float2 o = make_float2(
                            RATIO * (expf(acc[mt][nt][hh * 2] * DN - c) + EPS_),
                            RATIO * (expf(acc[mt][nt][hh * 2 + 1] * DN - c) + EPS_));
                        *(float2*)(dr + col) = o;
                    }
                }
            }
        }
    } else {
        // key path: store raw dash*DN; block max -> g_kmax[bh]
        float m = -INFINITY;
#pragma unroll
        for (int mt = 0; mt < 4; mt++) {
#pragma unroll
            for (int hh = 0; hh < 2; hh++) {
                int rl = warp_m * 64 + mt * 16 + (lane >> 2) + hh * 8;
                float* dr = dstp + (size_t)(row0 + rl) * NB_;
#pragma unroll
                for (int nt = 0; nt < 9; nt++) {
                    int col = warp_n * 72 + nt * 8 + (lane & 3) * 2;
                    if (col < NB_) {
                        float x = acc[mt][nt][hh * 2] * DN;
                        float y = acc[mt][nt][hh * 2 + 1] * DN;
                        m = fmaxf(m, fmaxf(x, y));
                        *(float2*)(dr + col) = make_float2(x, y);
                    }
                }
            }
        }
#pragma unroll
        for (int o = 16; o; o >>= 1) m = fmaxf(m, __shfl_xor_sync(0xffffffffu, m, o));
        if (lane == 0) atomicMaxF(&rmax_s[0], m);
        __syncthreads();
        if (tid == 0) atomicMaxF(&g_kmax[row0 >> 12], rmax_s[0]);
    }
}

// ---------------- k_sum (fused exp transform; deterministic two-stage) --------
__global__ void perf_ksumA_kernel() {
    const float RATIO = 0.06131393394849658f;
    int bh = blockIdx.y, ch = blockIdx.x, j = threadIdx.x;
    if (j >= NB_) return;
    float kmaxv = g_kmax[bh];
    const float* base = g_kp + ((size_t)(bh * N_ + ch * 128)) * NB_ + j;
    const float* dg = g_kdiag + bh * N_ + ch * 128;
    float s = 0.f;
#pragma unroll 4
    for (int r = 0; r < 128; r++)
        s += RATIO * (expf(base[(size_t)r * NB_] - dg[r] - kmaxv) + EPS_);
    g_ksum_part[(bh * 32 + ch) * NB_ + j] = s;
}

__global__ void perf_ksumB_kernel() {
    int bh = blockIdx.x, j = threadIdx.x;
    if (j >= NB_) return;
    float s = 0.f;
#pragma unroll
    for (int c = 0; c < 32; c++) s += g_ksum_part[(bh * 32 + c) * NB_ + j];
    g_ksum[bh * NB_ + j] = s;
}

// ---------------- ctx = kp^T v (exp transform fused into tile load) -----------
__global__ __launch_bounds__(256)
void perf_ctx_kernel() {
    const float RATIO = 0.06131393394849658f;
    __shared__ float kt[16][68];
    __shared__ float vt[16][68];
    int jt = blockIdx.x, ks = blockIdx.y, bh = blockIdx.z;
    int j0 = jt * 64, n0 = ks * 1024;
    int tid = threadIdx.x, tx = tid & 15, ty = tid >> 4;
    const float* kbase = g_kp + (size_t)bh * N_ * NB_;
    const float* vbase = g_v + (size_t)bh * N_ * DH_;
    const float* dgbase = g_kdiag + bh * N_;
    float kmaxv = g_kmax[bh];

    unsigned long long acc2[4][2];
#pragma unroll
    for (int a = 0; a < 4; a++) { acc2[a][0] = 0ull; acc2[a][1] = 0ull; }

    for (int nn = 0; nn < 1024; nn += 16) {
#pragma unroll
        for (int i = 0; i < 2; i++) {
            int id = i * 256 + tid;
            int r = id >> 5, c2 = id & 31;
            int j = j0 + c2 * 2;
            float2 o = make_float2(0.f, 0.f);
            if (j + 1 < NB_) {
                int row = n0 + nn + r;
                float c = dgbase[row] + kmaxv;
                float2 v = *(const float2*)(kbase + (size_t)row * NB_ + j);
                o.x = RATIO * (expf(v.x - c) + EPS_);
                o.y = RATIO * (expf(v.y - c) + EPS_);
            }
            kt[r][c2 * 2] = o.x;
            kt[r][c2 * 2 + 1] = o.y;
        }
        {
            int r = tid >> 4, c4 = tid & 15;
            float4 v = *(const float4*)(vbase + (size_t)(n0 + nn + r) * DH_ + c4 * 4);
            *(float4*)(&vt[r][c4 * 4]) = v;
        }
        __syncthreads();
#pragma unroll
        for (int k = 0; k < 16; k++) {
            float4 a = *(float4*)(&kt[k][ty * 4]);
            float4 b = *(float4*)(&vt[k][tx * 4]);
            unsigned long long b01 = pk2(b.x, b.y);
            unsigned long long b23 = pk2(b.z, b.w);
            float av[4] = {a.x, a.y, a.z, a.w};
#pragma unroll
            for (int i = 0; i < 4; i++) {
                unsigned long long ad = pk2(av[i], av[i]);
                ffma2(acc2[i][0], ad, b01);
                ffma2(acc2[i][1], ad, b23);
            }
        }
        __syncthreads();
    }

    float* obase = g_ctx_part + (size_t)(ks * BH_ + bh) * NB_ * DH_;
#pragma unroll
    for (int jj = 0; jj < 4; jj++) {
        int j = j0 + ty * 4 + jj;
        if (j < NB_) {
            float2 p0 = upk2(acc2[jj][0]);
            float2 p1 = upk2(acc2[jj][1]);
            *(float4*)(&obase[(size_t)j * DH_ + tx * 4]) =
                make_float4(p0.x, p0.y, p1.x, p1.y);
        }
    }
}

__global__ void perf_ctxred_kernel() {
    const int T = BH_ * NB_ * DH_;
    int i = blockIdx.x * blockDim.x + threadIdx.x;
    if (i >= T) return;
    g_ctx[i] = g_ctx_part[i] + g_ctx_part[i + T] + g_ctx_part[i + 2 * T] + g_ctx_part[i + 3 * T];
}

// ---------------- out = (qp @ ctx) / (qp @ ksum) ----------------
#define OUT_QS_W (8 * 272)
#define OUT_SMEM ((NB_ * DH_ + 268 + 16 * OUT_QS_W) * 4)

__global__ __launch_bounds__(512)
void perf_out_kernel(float* __restrict__ out) {
    extern __shared__ float sm[];
    float* ctx_s = sm;
    float* ksum_s = sm + NB_ * DH_;
    float* qsall = sm + NB_ * DH_ + 268;
    int tid = threadIdx.x, w = tid >> 5, lane = tid & 31;
    int row0 = blockIdx.x * 256;
    int bh = row0 >> 12;

    const float* cb = g_ctx + (size_t)bh * NB_ * DH_;
    for (int i = tid; i < NB_ * DH_ / 4; i += 512)
        *(float4*)(&ctx_s[i * 4]) = *(const float4*)(cb + i * 4);
    for (int i = tid; i < NB_; i += 512) ksum_s[i] = g_ksum[bh * NB_ + i];
    __syncthreads();

    int bb = bh / H_, h = bh - bb * H_;
    float* qs = qsall + w * OUT_QS_W;

    for (int grp = 0; grp < 2; grp++) {
        int rowg = row0 + w * 16 + grp * 8;

        __syncwarp();
#pragma unroll
        for (int r = 0; r < 8; r++) {
            const float2* qr = (const float2*)(g_qp + (size_t)(rowg + r) * NB_);
#pragma unroll
            for (int k = 0; k < 5; k++) {
                int idx = lane + 32 * k;
                if (idx < NB_ / 2) {
                    float2 v = qr[idx];
                    qs[r * 272 + idx * 2] = v.x;
                    qs[r * 272 + idx * 2 + 1] = v.y;
                }
            }
        }
        __syncwarp();

        float dinv[8];
#pragma unroll
        for (int r = 0; r < 8; r++) {
            float s = 0.f;
#pragma unroll
            for (int t = 0; t < 9; t++) {
                int j = lane + 32 * t;
                if (j < NB_) s += qs[r * 272 + j] * ksum_s[j];
            }
#pragma unroll
            for (int o = 16; o; o >>= 1) s += __shfl_xor_sync(0xffffffffu, s, o);
            dinv[r] = 1.0f / s;
        }

        unsigned long long acc2[8];
#pragma unroll
        for (int r = 0; r < 8; r++) acc2[r] = 0ull;

        for (int j0 = 0; j0 < 264; j0 += 4) {
            float qv[8][4];
#pragma unroll
            for (int r = 0; r < 8; r++)
                *(float4*)qv[r] = *(float4*)(&qs[r * 272 + j0]);
#pragma unroll
            for (int jj = 0; jj < 4; jj++) {
                unsigned long long c = *(const unsigned long long*)(&ctx_s[(j0 + jj) * 64 + 2 * lane]);
#pragma unroll
                for (int r = 0; r < 8; r++) {
                    unsigned long long ad = pk2(qv[r][jj], qv[r][jj]);
                    ffma2(acc2[r], ad, c);
                }
            }
        }
#pragma unroll
        for (int jj = 264; jj < NB_; jj++) {
            unsigned long long c = *(const unsigned long long*)(&ctx_s[jj * 64 + 2 * lane]);
#pragma unroll
            for (int r = 0; r < 8; r++) {
                float qv = qs[r * 272 + jj];
                unsigned long long ad = pk2(qv, qv);
                ffma2(acc2[r], ad, c);
            }
        }

#pragma unroll
        for (int r = 0; r < 8; r++) {
            int row = rowg + r;
            int n = row & (N_ - 1);
            float2 u = upk2(acc2[r]);
            *(float2*)(out + ((size_t)(bb * N_ + n)) * 768 + h * 64 + 2 * lane) =
                make_float2(u.x * dinv[r], u.y * dinv[r]);
        }
    }
}

// ---------------- launch ----------------
extern "C" void kernel_launch(void* const* d_in, const int* in_sizes, int n_in,
                              void* d_out, int out_size) {
    (void)in_sizes; (void)n_in; (void)out_size;
    const float* hs   = (const float*)d_in[0];
    const float* Wq   = (const float*)d_in[1];
    const float* bq   = (const float*)d_in[2];
    const float* Wk   = (const float*)d_in[3];
    const float* bk   = (const float*)d_in[4];
    const float* Wv   = (const float*)d_in[5];
    const float* bv   = (const float*)d_in[6];
    const float* proj = (const float*)d_in[7];
    float* out = (float*)d_out;

    cudaFuncSetAttribute(perf_qkv_mma,  cudaFuncAttributeMaxDynamicSharedMemorySize, QKV_SMEM);
    cudaFuncSetAttribute(perf_feat_mma, cudaFuncAttributeMaxDynamicSharedMemorySize, FEAT_SMEM);
    cudaFuncSetAttribute(perf_out_kernel, cudaFuncAttributeMaxDynamicSharedMemorySize, OUT_SMEM);

    perf_init_kernel<<<1, 64>>>();
    perf_cvt_a<<<(16384 * 768 / 4 + 255) / 256, 256>>>(hs);
    perf_cvt_w<<<(2304 * 768 / 4 + 255) / 256, 256>>>(Wq, Wk, Wv);
    perf_cvt_p<<<(288 * 64 / 4 + 255) / 256, 256>>>(proj);
    perf_qkv_mma<<<dim3(128, 18), 128, QKV_SMEM>>>(bq, bk, bv);
    perf_feat_mma<<<dim3(R_ / 128, 2), 256, FEAT_SMEM>>>();
    perf_ksumA_kernel<<<dim3(32, BH_), 288>>>();
    perf_ksumB_kernel<<<BH_, 288>>>();
    perf_ctx_kernel<<<dim3(5, 4, BH_), 256>>>();
    perf_ctxred_kernel<<<(BH_ * NB_ * DH_ + 255) / 256, 256>>>();
    perf_out_kernel<<<R_ / 256, 512, OUT_SMEM>>>(out);
}

// round 16
// speedup vs baseline: 2.8620x; 1.0395x over previous
#include <cuda_runtime.h>
#include <cuda_bf16.h>
#include <math.h>

#define B_   4
#define N_   4096
#define H_   12
#define DH_  64
#define NB_  266
#define BH_  (B_*H_)           // 48
#define R_   (B_*H_*N_)        // 196608
#define EPS_ 1e-4f

// ---------------- scratch (static device memory; no allocation) ----------------
__device__ float g_v[R_ * DH_];
__device__ float g_qp[R_ * NB_];
__device__ float g_kp[R_ * NB_];           // raw dash (never transformed in place)
__device__ float g_qdiag[R_];
__device__ float g_kdiag[R_];
__device__ float g_kmax[BH_];
__device__ float g_ksum_part[4 * BH_ * NB_];
__device__ float g_ksum[BH_ * NB_];
__device__ float g_ctx_part[4 * BH_ * NB_ * DH_];
__device__ float g_ctx[BH_ * NB_ * DH_];
// bf16 hi/lo split operands
__device__ __nv_bfloat16 g_ahi[16384 * 768];
__device__ __nv_bfloat16 g_alo[16384 * 768];
__device__ __nv_bfloat16 g_whi[2304 * 768];
__device__ __nv_bfloat16 g_wlo[2304 * 768];
__device__ __nv_bfloat16 g_qhi[R_ * DH_];
__device__ __nv_bfloat16 g_qlo[R_ * DH_];
__device__ __nv_bfloat16 g_khi[R_ * DH_];
__device__ __nv_bfloat16 g_klo[R_ * DH_];
__device__ __nv_bfloat16 g_phi[288 * DH_];
__device__ __nv_bfloat16 g_plo[288 * DH_];

// ---------------- helpers ----------------
static __device__ __forceinline__ unsigned long long pk2(float lo, float hi) {
    unsigned long long r;
    asm("mov.b64 %0, {%1, %2};" : "=l"(r) : "f"(lo), "f"(hi));
    return r;
}
static __device__ __forceinline__ float2 upk2(unsigned long long v) {
    float2 r;
    asm("mov.b64 {%0, %1}, %2;" : "=f"(r.x), "=f"(r.y) : "l"(v));
    return r;
}
static __device__ __forceinline__ void ffma2(unsigned long long& d,
                                             unsigned long long a,
                                             unsigned long long b) {
    asm("fma.rn.f32x2 %0, %1, %2, %0;" : "+l"(d) : "l"(a), "l"(b));
}
static __device__ __forceinline__ void atomicMaxF(float* addr, float v) {
    if (v >= 0.f) atomicMax((int*)addr, __float_as_int(v));
    else          atomicMin((unsigned int*)addr, __float_as_uint(v));
}
static __device__ __forceinline__ unsigned smem_u32(const void* p) {
    unsigned a;
    asm("{ .reg .u64 t; cvta.to.shared.u64 t, %1; cvt.u32.u64 %0, t; }" : "=r"(a) : "l"(p));
    return a;
}

static __device__ __forceinline__ void ldmx4(unsigned& r0, unsigned& r1,
                                             unsigned& r2, unsigned& r3, unsigned a) {
    asm volatile("ldmatrix.sync.aligned.m8n8.x4.shared.b16 {%0,%1,%2,%3}, [%4];"
                 : "=r"(r0), "=r"(r1), "=r"(r2), "=r"(r3) : "r"(a));
}
static __device__ __forceinline__ void ldmx2(unsigned& r0, unsigned& r1, unsigned a) {
    asm volatile("ldmatrix.sync.aligned.m8n8.x2.shared.b16 {%0,%1}, [%2];"
                 : "=r"(r0), "=r"(r1) : "r"(a));
}
static __device__ __forceinline__ void mma16816(float* c, const unsigned* a,
                                                const unsigned* b) {
    asm volatile(
        "mma.sync.aligned.m16n8k16.row.col.f32.bf16.bf16.f32 "
        "{%0,%1,%2,%3}, {%4,%5,%6,%7}, {%8,%9}, {%0,%1,%2,%3};"
        : "+f"(c[0]), "+f"(c[1]), "+f"(c[2]), "+f"(c[3])
        : "r"(a[0]), "r"(a[1]), "r"(a[2]), "r"(a[3]), "r"(b[0]), "r"(b[1]));
}

#define CP16(dst, src) \
    asm volatile("cp.async.ca.shared.global [%0], [%1], 16;" :: "r"(dst), "l"(src))
#define CP_COMMIT() asm volatile("cp.async.commit_group;" ::: "memory")
#define CP_WAIT1()  asm volatile("cp.async.wait_group 1;" ::: "memory")
#define CP_WAIT0()  asm volatile("cp.async.wait_group 0;" ::: "memory")

__global__ void perf_init_kernel() {
    if (threadIdx.x < BH_) g_kmax[threadIdx.x] = -INFINITY;
}

// ---------------- hi/lo bf16 splits ----------------
__global__ __launch_bounds__(256)
void perf_cvt_a(const float* __restrict__ hs) {
    int i = blockIdx.x * blockDim.x + threadIdx.x;      // float4 index
    const int T4 = 16384 * 768 / 4;
    if (i >= T4) return;
    float4 v = ((const float4*)hs)[i];
    __nv_bfloat16 hx = __float2bfloat16_rn(v.x), hy = __float2bfloat16_rn(v.y);
    __nv_bfloat16 hz = __float2bfloat16_rn(v.z), hw = __float2bfloat16_rn(v.w);
    __nv_bfloat162* ph = (__nv_bfloat162*)(g_ahi + i * 4);
    ph[0] = __nv_bfloat162(hx, hy);
    ph[1] = __nv_bfloat162(hz, hw);
    __nv_bfloat162* pl = (__nv_bfloat162*)(g_alo + i * 4);
    pl[0] = __nv_bfloat162(__float2bfloat16_rn(v.x - __bfloat162float(hx)),
                           __float2bfloat16_rn(v.y - __bfloat162float(hy)));
    pl[1] = __nv_bfloat162(__float2bfloat16_rn(v.z - __bfloat162float(hz)),
                           __float2bfloat16_rn(v.w - __bfloat162float(hw)));
}

__global__ __launch_bounds__(256)
void perf_cvt_w(const float* __restrict__ Wq, const float* __restrict__ Wk,
                const float* __restrict__ Wv) {
    int i = blockIdx.x * blockDim.x + threadIdx.x;      // float4 index
    const int T4 = 2304 * 768 / 4;
    if (i >= T4) return;
    int e = i * 4;
    int row = e / 768, col = e - row * 768;
    int z = row / 768;
    const float* W = (z == 0) ? Wq : (z == 1) ? Wk : Wv;
    float4 v = *(const float4*)(W + (size_t)(row - z * 768) * 768 + col);
    __nv_bfloat16 hx = __float2bfloat16_rn(v.x), hy = __float2bfloat16_rn(v.y);
    __nv_bfloat16 hz = __float2bfloat16_rn(v.z), hw = __float2bfloat16_rn(v.w);
    __nv_bfloat162* ph = (__nv_bfloat162*)(g_whi + e);
    ph[0] = __nv_bfloat162(hx, hy);
    ph[1] = __nv_bfloat162(hz, hw);
    __nv_bfloat162* pl = (__nv_bfloat162*)(g_wlo + e);
    pl[0] = __nv_bfloat162(__float2bfloat16_rn(v.x - __bfloat162float(hx)),
                           __float2bfloat16_rn(v.y - __bfloat162float(hy)));
    pl[1] = __nv_bfloat162(__float2bfloat16_rn(v.z - __bfloat162float(hz)),
                           __float2bfloat16_rn(v.w - __bfloat162float(hw)));
}

__global__ __launch_bounds__(256)
void perf_cvt_p(const float* __restrict__ proj) {
    int i = blockIdx.x * blockDim.x + threadIdx.x;      // float4 index
    const int T4 = 288 * 64 / 4;
    if (i >= T4) return;
    int e = i * 4;
    int row = e >> 6;
    float4 v = make_float4(0.f, 0.f, 0.f, 0.f);
    if (row < NB_) v = *(const float4*)(proj + e);
    __nv_bfloat16 hx = __float2bfloat16_rn(v.x), hy = __float2bfloat16_rn(v.y);
    __nv_bfloat16 hz = __float2bfloat16_rn(v.z), hw = __float2bfloat16_rn(v.w);
    __nv_bfloat162* ph = (__nv_bfloat162*)(g_phi + e);
    ph[0] = __nv_bfloat162(hx, hy);
    ph[1] = __nv_bfloat162(hz, hw);
    __nv_bfloat162* pl = (__nv_bfloat162*)(g_plo + e);
    pl[0] = __nv_bfloat162(__float2bfloat16_rn(v.x - __bfloat162float(hx)),
                           __float2bfloat16_rn(v.y - __bfloat162float(hy)));
    pl[1] = __nv_bfloat162(__float2bfloat16_rn(v.z - __bfloat162float(hz)),
                           __float2bfloat16_rn(v.w - __bfloat162float(hw)));
}

// ---------------- QKV GEMM on HMMA: block 128x128, 4 warps 64x64, cp.async x2 --
// Epilogue also computes per-row diag (sum x^2) for q and k.
#define QROW 80
#define S_AH 0
#define S_AL (128 * QROW)
#define S_BH (2 * 128 * QROW)
#define S_BL (3 * 128 * QROW)
#define SSTAGE (4 * 128 * QROW)              // 40960 bytes
#define QKV_SMEM (2 * SSTAGE + 128 * 4)

__global__ __launch_bounds__(128, 2)
void perf_qkv_mma(const float* __restrict__ bq, const float* __restrict__ bk,
                  const float* __restrict__ bv) {
    extern __shared__ __align__(16) unsigned char smq[];
    float* bias_s = (float*)(smq + 2 * SSTAGE);
    unsigned sb = smem_u32(smq);

    int tid = threadIdx.x, wid = tid >> 5, lane = tid & 31;
    int warp_m = wid & 1, warp_n = wid >> 1;          // 2 x 2 grid of 64x64 tiles
    int m0 = blockIdx.x * 128;
    int n0 = blockIdx.y * 128;                        // row in concatenated W [2304]
    int z = blockIdx.y / 6;                           // 0=q, 1=k, 2=v
    int o_base = (blockIdx.y - z * 6) * 128;
    const float* bias = (z == 0) ? bq : (z == 1) ? bk : bv;
    bias_s[tid] = bias[o_base + tid];

    float acc[4][8][4];
#pragma unroll
    for (int mt = 0; mt < 4; mt++)
#pragma unroll
        for (int nt = 0; nt < 8; nt++)
#pragma unroll
            for (int e = 0; e < 4; e++) acc[mt][nt][e] = 0.f;

    int rA = tid >> 2, segA = tid & 3;

    {
        int k0 = 0;
        unsigned st = sb;
#pragma unroll
        for (int i = 0; i < 4; i++) {
            int r = rA + i * 32;
            size_t go = (size_t)(m0 + r) * 768 + k0 + segA * 8;
            unsigned so = (unsigned)(r * QROW + segA * 16);
            CP16(st + S_AH + so, g_ahi + go);
            CP16(st + S_AL + so, g_alo + go);
            size_t gb = (size_t)(n0 + r) * 768 + k0 + segA * 8;
            CP16(st + S_BH + so, g_whi + gb);
            CP16(st + S_BL + so, g_wlo + gb);
        }
        CP_COMMIT();
    }

    for (int ch = 0; ch < 24; ch++) {
        unsigned st = sb + (unsigned)((ch & 1) * SSTAGE);
        if (ch < 23) {
            int k0 = (ch + 1) * 32;
            unsigned st2 = sb + (unsigned)(((ch + 1) & 1) * SSTAGE);
#pragma unroll
            for (int i = 0; i < 4; i++) {
                int r = rA + i * 32;
                size_t go = (size_t)(m0 + r) * 768 + k0 + segA * 8;
                unsigned so = (unsigned)(r * QROW + segA * 16);
                CP16(st2 + S_AH + so, g_ahi + go);
                CP16(st2 + S_AL + so, g_alo + go);
                size_t gb = (size_t)(n0 + r) * 768 + k0 + segA * 8;
                CP16(st2 + S_BH + so, g_whi + gb);
                CP16(st2 + S_BL + so, g_wlo + gb);
            }
            CP_COMMIT();
            CP_WAIT1();
        } else {
            CP_WAIT0();
        }
        __syncthreads();

#pragma unroll
        for (int ks = 0; ks < 2; ks++) {
            unsigned ah[4][4], al[4][4];
#pragma unroll
            for (int mt = 0; mt < 4; mt++) {
                unsigned ra = (unsigned)((warp_m * 64 + mt * 16 + (lane & 15)) * QROW +
                                         ks * 32 + (lane >> 4) * 16);
                ldmx4(ah[mt][0], ah[mt][1], ah[mt][2], ah[mt][3], st + S_AH + ra);
                ldmx4(al[mt][0], al[mt][1], al[mt][2], al[mt][3], st + S_AL + ra);
            }
#pragma unroll
            for (int nt = 0; nt < 8; nt++) {
                unsigned rb = (unsigned)((warp_n * 64 + nt * 8 + (lane & 7)) * QROW +
                                         ks * 32 + ((lane >> 3) & 1) * 16);
                unsigned bh[2], bl[2];
                ldmx2(bh[0], bh[1], st + S_BH + rb);
                ldmx2(bl[0], bl[1], st + S_BL + rb);
#pragma unroll
                for (int mt = 0; mt < 4; mt++) {
                    mma16816(acc[mt][nt], ah[mt], bh);
                    mma16816(acc[mt][nt], ah[mt], bl);
                    mma16816(acc[mt][nt], al[mt], bh);
                }
            }
        }
        __syncthreads();
    }

    // epilogue: add bias; q/k -> bf16 hi/lo + diag, v -> fp32
#pragma unroll
    for (int mt = 0; mt < 4; mt++) {
        float dsum[2] = {0.f, 0.f};
#pragma unroll
        for (int nt = 0; nt < 8; nt++) {
            int cb = warp_n * 64 + nt * 8 + (lane & 3) * 2;
            int oc = o_base + cb;
            int h = oc >> 6, d = oc & 63;
            float bx = bias_s[cb], by = bias_s[cb + 1];
#pragma unroll
            for (int hh = 0; hh < 2; hh++) {
                int gi = m0 + warp_m * 64 + mt * 16 + (lane >> 2) + hh * 8;
                int bbi = gi >> 12, nn = gi & (N_ - 1);
                size_t idx = ((size_t)(bbi * H_ + h) * N_ + nn) * DH_ + d;
                float vx = acc[mt][nt][hh * 2 + 0] + bx;
                float vy = acc[mt][nt][hh * 2 + 1] + by;
                if (z == 2) {
                    *(float2*)(g_v + idx) = make_float2(vx, vy);
                } else {
                    dsum[hh] += vx * vx + vy * vy;
                    __nv_bfloat16* dh = z ? g_khi : g_qhi;
                    __nv_bfloat16* dl = z ? g_klo : g_qlo;
                    __nv_bfloat16 hx = __float2bfloat16_rn(vx);
                    __nv_bfloat16 hy = __float2bfloat16_rn(vy);
                    *(__nv_bfloat162*)(dh + idx) = __nv_bfloat162(hx, hy);
                    *(__nv_bfloat162*)(dl + idx) = __nv_bfloat162(
                        __float2bfloat16_rn(vx - __bfloat162float(hx)),
                        __float2bfloat16_rn(vy - __bfloat162float(hy)));
                }
            }
        }
        if (z < 2) {
            float* dgout = z ? g_kdiag : g_qdiag;
            int h = (o_base + warp_n * 64) >> 6;
#pragma unroll
            for (int hh = 0; hh < 2; hh++) {
                float s = dsum[hh];
                s += __shfl_xor_sync(0xffffffffu, s, 1);
                s += __shfl_xor_sync(0xffffffffu, s, 2);
                if ((lane & 3) == 0) {
                    int gi = m0 + warp_m * 64 + mt * 16 + (lane >> 2) + hh * 8;
                    int bbi = gi >> 12, nn = gi & (N_ - 1);
                    dgout[(size_t)(bbi * H_ + h) * N_ + nn] = 0.0625f * s;
                }
            }
        }
    }
}

// ---------------- FAVOR+ feature map on HMMA --------------------------------
// Block: 128 rows x 288 cols. 8 warps (2m x 4n), warp 64x72.
// diag preloaded from gmem (computed in QKV epilogue).
#define FROW 144
#define FS_QH 0
#define FS_QL (128 * FROW)
#define FS_PH (2 * 128 * FROW)
#define FS_PL (FS_PH + 288 * FROW)
#define FS_DIAG (FS_PL + 288 * FROW)          // 119808
#define FS_RMAX (FS_DIAG + 512)
#define FEAT_SMEM (FS_RMAX + 512)

__global__ __launch_bounds__(256)
void perf_feat_mma() {
    extern __shared__ __align__(16) unsigned char smf[];
    float* diag_s = (float*)(smf + FS_DIAG);
    float* rmax_s = (float*)(smf + FS_RMAX);
    unsigned sb = smem_u32(smf);

    int tid = threadIdx.x, wid = tid >> 5, lane = tid & 31;
    int warp_m = wid & 1, warp_n = wid >> 1;
    int which = blockIdx.y;
    int row0 = blockIdx.x * 128;
    const __nv_bfloat16* srcH = which ? g_khi : g_qhi;
    const __nv_bfloat16* srcL = which ? g_klo : g_qlo;
    float* dstp = which ? g_kp : g_qp;

    if (tid < 128) {
        rmax_s[tid] = -INFINITY;
        diag_s[tid] = which ? g_kdiag[row0 + tid] : g_qdiag[row0 + tid];
    }

    for (int i = tid; i < 128 * 8; i += 256) {
        int r = i >> 3, c = i & 7;
        *(uint4*)(smf + FS_QH + r * FROW + c * 16) =
            *(const uint4*)(srcH + (size_t)(row0 + r) * 64 + c * 8);
        *(uint4*)(smf + FS_QL + r * FROW + c * 16) =
            *(const uint4*)(srcL + (size_t)(row0 + r) * 64 + c * 8);
    }
    for (int i = tid; i < 288 * 8; i += 256) {
        int r = i >> 3, c = i & 7;
        *(uint4*)(smf + FS_PH + r * FROW + c * 16) = *(const uint4*)(g_phi + r * 64 + c * 8);
        *(uint4*)(smf + FS_PL + r * FROW + c * 16) = *(const uint4*)(g_plo + r * 64 + c * 8);
    }
    __syncthreads();

    float acc[4][9][4];
#pragma unroll
    for (int mt = 0; mt < 4; mt++)
#pragma unroll
        for (int nt = 0; nt < 9; nt++)
#pragma unroll
            for (int e = 0; e < 4; e++) acc[mt][nt][e] = 0.f;

#pragma unroll
    for (int ks = 0; ks < 4; ks++) {
        unsigned ah[4][4], al[4][4];
#pragma unroll
        for (int mt = 0; mt < 4; mt++) {
            unsigned ra = (unsigned)((warp_m * 64 + mt * 16 + (lane & 15)) * FROW +
                                     ks * 32 + (lane >> 4) * 16);
            ldmx4(ah[mt][0], ah[mt][1], ah[mt][2], ah[mt][3], sb + FS_QH + ra);
            ldmx4(al[mt][0], al[mt][1], al[mt][2], al[mt][3], sb + FS_QL + ra);
        }
#pragma unroll
        for (int nt = 0; nt < 9; nt++) {
            unsigned rb = (unsigned)((warp_n * 72 + nt * 8 + (lane & 7)) * FROW +
                                     ks * 32 + ((lane >> 3) & 1) * 16);
            unsigned bh[2], bl[2];
            ldmx2(bh[0], bh[1], sb + FS_PH + rb);
            ldmx2(bl[0], bl[1], sb + FS_PL + rb);
#pragma unroll
            for (int mt = 0; mt < 4; mt++) {
                mma16816(acc[mt][nt], ah[mt], bh);
                mma16816(acc[mt][nt], ah[mt], bl);
                mma16816(acc[mt][nt], al[mt], bh);
            }
        }
    }

    const float DN = 0.3535533905932738f;      // 64^-0.25
    const float RATIO = 0.06131393394849658f;  // 266^-0.5

    if (which == 0) {
#pragma unroll
        for (int mt = 0; mt < 4; mt++) {
#pragma unroll
            for (int hh = 0; hh < 2; hh++) {
                float m = -INFINITY;
#pragma unroll
                for (int nt = 0; nt < 9; nt++) {
                    int col = warp_n * 72 + nt * 8 + (lane & 3) * 2;
                    if (col < NB_)
                        m = fmaxf(m, fmaxf(acc[mt][nt][hh * 2], acc[mt][nt][hh * 2 + 1]));
                }
                m = fmaxf(m, __shfl_xor_sync(0xffffffffu, m, 1));
                m = fmaxf(m, __shfl_xor_sync(0xffffffffu, m, 2));
                if ((lane & 3) == 0)
                    atomicMaxF(&rmax_s[warp_m * 64 + mt * 16 + (lane >> 2) + hh * 8], m * DN);
            }
        }
        __syncthreads();
#pragma unroll
        for (int mt = 0; mt < 4; mt++) {
#pragma unroll
            for (int hh = 0; hh < 2; hh++) {
                int rl = warp_m * 64 + mt * 16 + (lane >> 2) + hh * 8;
                float c = diag_s[rl] + rmax_s[rl];
                float* dr = dstp + (size_t)(row0 + rl) * NB_;
#pragma unroll
                for (int nt = 0; nt < 9; nt++) {
                    int col = warp_n * 72 + nt * 8 + (lane & 3) * 2;
                    if (col < NB_) {
                        float2 o = make_float2(
                            RATIO * (expf(acc[mt][nt][hh * 2] * DN - c) + EPS_),
                            RATIO * (expf(acc[mt][nt][hh * 2 + 1] * DN - c) + EPS_));
                        *(float2*)(dr + col) = o;
                    }
                }
            }
        }
    } else {
        // key path: store raw dash*DN; block max -> g_kmax[bh]
        float m = -INFINITY;
#pragma unroll
        for (int mt = 0; mt < 4; mt++) {
#pragma unroll
            for (int hh = 0; hh < 2; hh++) {
                int rl = warp_m * 64 + mt * 16 + (lane >> 2) + hh * 8;
                float* dr = dstp + (size_t)(row0 + rl) * NB_;
#pragma unroll
                for (int nt = 0; nt < 9; nt++) {
                    int col = warp_n * 72 + nt * 8 + (lane & 3) * 2;
                    if (col < NB_) {
                        float x = acc[mt][nt][hh * 2] * DN;
                        float y = acc[mt][nt][hh * 2 + 1] * DN;
                        m = fmaxf(m, fmaxf(x, y));
                        *(float2*)(dr + col) = make_float2(x, y);
                    }
                }
            }
        }
#pragma unroll
        for (int o = 16; o; o >>= 1) m = fmaxf(m, __shfl_xor_sync(0xffffffffu, m, o));
        if (lane == 0) atomicMaxF(&rmax_s[0], m);
        __syncthreads();
        if (tid == 0) atomicMaxF(&g_kmax[row0 >> 12], rmax_s[0]);
    }
}

// ---------------- ctx = kp^T v + fused exp + fused partial ksum ---------------
__global__ __launch_bounds__(256)
void perf_ctx_kernel() {
    const float RATIO = 0.06131393394849658f;
    __shared__ float kt[16][68];
    __shared__ float vt[16][68];
    __shared__ float red[8][64];
    int jt = blockIdx.x, kspl = blockIdx.y, bh = blockIdx.z;
    int j0 = jt * 64, n0 = kspl * 1024;
    int tid = threadIdx.x, tx = tid & 15, ty = tid >> 4;
    const float* kbase = g_kp + (size_t)bh * N_ * NB_;
    const float* vbase = g_v + (size_t)bh * N_ * DH_;
    const float* dgbase = g_kdiag + bh * N_;
    float kmaxv = g_kmax[bh];

    unsigned long long acc2[4][2];
#pragma unroll
    for (int a = 0; a < 4; a++) { acc2[a][0] = 0ull; acc2[a][1] = 0ull; }
    float ks0 = 0.f, ks1 = 0.f;          // column sums (fused ksum partial)

    for (int nn = 0; nn < 1024; nn += 16) {
#pragma unroll
        for (int i = 0; i < 2; i++) {
            int id = i * 256 + tid;
            int r = id >> 5, c2 = id & 31;
            int j = j0 + c2 * 2;
            float2 o = make_float2(0.f, 0.f);
            if (j + 1 < NB_) {
                int row = n0 + nn + r;
                float c = dgbase[row] + kmaxv;
                float2 v = *(const float2*)(kbase + (size_t)row * NB_ + j);
                o.x = RATIO * (expf(v.x - c) + EPS_);
                o.y = RATIO * (expf(v.y - c) + EPS_);
            }
            ks0 += o.x;
            ks1 += o.y;
            kt[r][c2 * 2] = o.x;
            kt[r][c2 * 2 + 1] = o.y;
        }
        {
            int r = tid >> 4, c4 = tid & 15;
            float4 v = *(const float4*)(vbase + (size_t)(n0 + nn + r) * DH_ + c4 * 4);
            *(float4*)(&vt[r][c4 * 4]) = v;
        }
        __syncthreads();
#pragma unroll
        for (int k = 0; k < 16; k++) {
            float4 a = *(float4*)(&kt[k][ty * 4]);
            float4 b = *(float4*)(&vt[k][tx * 4]);
            unsigned long long b01 = pk2(b.x, b.y);
            unsigned long long b23 = pk2(b.z, b.w);
            float av[4] = {a.x, a.y, a.z, a.w};
#pragma unroll
            for (int i = 0; i < 4; i++) {
                unsigned long long ad = pk2(av[i], av[i]);
                ffma2(acc2[i][0], ad, b01);
                ffma2(acc2[i][1], ad, b23);
            }
        }
        __syncthreads();
    }

    // deterministic ksum partial: 8 row-groups x 64 cols -> fixed-order sum
    {
        int rg = tid >> 5, c2 = tid & 31;
        red[rg][c2 * 2] = ks0;
        red[rg][c2 * 2 + 1] = ks1;
    }
    __syncthreads();
    if (tid < 64) {
        float s = 0.f;
#pragma unroll
        for (int g = 0; g < 8; g++) s += red[g][tid];
        int j = j0 + tid;
        if (j < NB_) g_ksum_part[(bh * 4 + kspl) * NB_ + j] = s;
    }

    float* obase = g_ctx_part + (size_t)(kspl * BH_ + bh) * NB_ * DH_;
#pragma unroll
    for (int jj = 0; jj < 4; jj++) {
        int j = j0 + ty * 4 + jj;
        if (j < NB_) {
            float2 p0 = upk2(acc2[jj][0]);
            float2 p1 = upk2(acc2[jj][1]);
            *(float4*)(&obase[(size_t)j * DH_ + tx * 4]) =
                make_float4(p0.x, p0.y, p1.x, p1.y);
        }
    }
}

__global__ void perf_ksumB_kernel() {
    int bh = blockIdx.x, j = threadIdx.x;
    if (j >= NB_) return;
    float s = 0.f;
#pragma unroll
    for (int c = 0; c < 4; c++) s += g_ksum_part[(bh * 4 + c) * NB_ + j];
    g_ksum[bh * NB_ + j] = s;
}

__global__ void perf_ctxred_kernel() {
    const int T = BH_ * NB_ * DH_;
    int i = blockIdx.x * blockDim.x + threadIdx.x;
    if (i >= T) return;
    g_ctx[i] = g_ctx_part[i] + g_ctx_part[i + T] + g_ctx_part[i + 2 * T] + g_ctx_part[i + 3 * T];
}

// ---------------- out = (qp @ ctx) / (qp @ ksum) ----------------
#define OUT_QS_W (8 * 272)
#define OUT_SMEM ((NB_ * DH_ + 268 + 16 * OUT_QS_W) * 4)

__global__ __launch_bounds__(512)
void perf_out_kernel(float* __restrict__ out) {
    extern __shared__ float sm[];
    float* ctx_s = sm;
    float* ksum_s = sm + NB_ * DH_;
    float* qsall = sm + NB_ * DH_ + 268;
    int tid = threadIdx.x, w = tid >> 5, lane = tid & 31;
    int row0 = blockIdx.x * 256;
    int bh = row0 >> 12;

    const float* cb = g_ctx + (size_t)bh * NB_ * DH_;
    for (int i = tid; i < NB_ * DH_ / 4; i += 512)
        *(float4*)(&ctx_s[i * 4]) = *(const float4*)(cb + i * 4);
    for (int i = tid; i < NB_; i += 512) ksum_s[i] = g_ksum[bh * NB_ + i];
    __syncthreads();

    int bb = bh / H_, h = bh - bb * H_;
    float* qs = qsall + w * OUT_QS_W;

    for (int grp = 0; grp < 2; grp++) {
        int rowg = row0 + w * 16 + grp * 8;

        __syncwarp();
#pragma unroll
        for (int r = 0; r < 8; r++) {
            const float2* qr = (const float2*)(g_qp + (size_t)(rowg + r) * NB_);
#pragma unroll
            for (int k = 0; k < 5; k++) {
                int idx = lane + 32 * k;
                if (idx < NB_ / 2) {
                    float2 v = qr[idx];
                    qs[r * 272 + idx * 2] = v.x;
                    qs[r * 272 + idx * 2 + 1] = v.y;
                }
            }
        }
        __syncwarp();

        float dinv[8];
#pragma unroll
        for (int r = 0; r < 8; r++) {
            float s = 0.f;
#pragma unroll
            for (int t = 0; t < 9; t++) {
                int j = lane + 32 * t;
                if (j < NB_) s += qs[r * 272 + j] * ksum_s[j];
            }
#pragma unroll
            for (int o = 16; o; o >>= 1) s += __shfl_xor_sync(0xffffffffu, s, o);
            dinv[r] = 1.0f / s;
        }

        unsigned long long acc2[8];
#pragma unroll
        for (int r = 0; r < 8; r++) acc2[r] = 0ull;

        for (int j0 = 0; j0 < 264; j0 += 4) {
            float qv[8][4];
#pragma unroll
            for (int r = 0; r < 8; r++)
                *(float4*)qv[r] = *(float4*)(&qs[r * 272 + j0]);
#pragma unroll
            for (int jj = 0; jj < 4; jj++) {
                unsigned long long c = *(const unsigned long long*)(&ctx_s[(j0 + jj) * 64 + 2 * lane]);
#pragma unroll
                for (int r = 0; r < 8; r++) {
                    unsigned long long ad = pk2(qv[r][jj], qv[r][jj]);
                    ffma2(acc2[r], ad, c);
                }
            }
        }
#pragma unroll
        for (int jj = 264; jj < NB_; jj++) {
            unsigned long long c = *(const unsigned long long*)(&ctx_s[jj * 64 + 2 * lane]);
#pragma unroll
            for (int r = 0; r < 8; r++) {
                float qv = qs[r * 272 + jj];
                unsigned long long ad = pk2(qv, qv);
                ffma2(acc2[r], ad, c);
            }
        }

#pragma unroll
        for (int r = 0; r < 8; r++) {
            int row = rowg + r;
            int n = row & (N_ - 1);
            float2 u = upk2(acc2[r]);
            *(float2*)(out + ((size_t)(bb * N_ + n)) * 768 + h * 64 + 2 * lane) =
                make_float2(u.x * dinv[r], u.y * dinv[r]);
        }
    }
}

// ---------------- launch ----------------
extern "C" void kernel_launch(void* const* d_in, const int* in_sizes, int n_in,
                              void* d_out, int out_size) {
    (void)in_sizes; (void)n_in; (void)out_size;
    const float* hs   = (const float*)d_in[0];
    const float* Wq   = (const float*)d_in[1];
    const float* bq   = (const float*)d_in[2];
    const float* Wk   = (const float*)d_in[3];
    const float* bk   = (const float*)d_in[4];
    const float* Wv   = (const float*)d_in[5];
    const float* bv   = (const float*)d_in[6];
    const float* proj = (const float*)d_in[7];
    float* out = (float*)d_out;

    cudaFuncSetAttribute(perf_qkv_mma,  cudaFuncAttributeMaxDynamicSharedMemorySize, QKV_SMEM);
    cudaFuncSetAttribute(perf_feat_mma, cudaFuncAttributeMaxDynamicSharedMemorySize, FEAT_SMEM);
    cudaFuncSetAttribute(perf_out_kernel, cudaFuncAttributeMaxDynamicSharedMemorySize, OUT_SMEM);

    perf_init_kernel<<<1, 64>>>();
    perf_cvt_a<<<(16384 * 768 / 4 + 255) / 256, 256>>>(hs);
    perf_cvt_w<<<(2304 * 768 / 4 + 255) / 256, 256>>>(Wq, Wk, Wv);
    perf_cvt_p<<<(288 * 64 / 4 + 255) / 256, 256>>>(proj);
    perf_qkv_mma<<<dim3(128, 18), 128, QKV_SMEM>>>(bq, bk, bv);
    perf_feat_mma<<<dim3(R_ / 128, 2), 256, FEAT_SMEM>>>();
    perf_ctx_kernel<<<dim3(5, 4, BH_), 256>>>();
    perf_ksumB_kernel<<<BH_, 288>>>();
    perf_ctxred_kernel<<<(BH_ * NB_ * DH_ + 255) / 256, 256>>>();
    perf_out_kernel<<<R_ / 256, 512, OUT_SMEM>>>(out);
}